// round 6
// baseline (speedup 1.0000x reference)
#include <cuda_runtime.h>
#include <cuda_bf16.h>
#include <math.h>
#include <stdint.h>

#define B_   8
#define S_   512
#define DIN  1024
#define DOUT 1024
#define H_   8
#define DATT 128
#define NTOK (B_ * S_)   // 4096

// ---------------- device scratch (no allocation allowed) ----------------
__device__ __align__(16) float    g_xp[NTOK * DOUT];        // projected x [token][chan]
__device__ __align__(16) float    g_e2[B_ * H_ * S_];       // masked exp(s2 - max)
__device__ __align__(16) float    g_colsum[B_ * DOUT];      // column sums (fallback)
__device__ __align__(16) uint16_t g_xh[NTOK * DIN];         // x hi bf16
__device__ __align__(16) uint16_t g_xl[NTOK * DIN];         // x lo bf16
__device__ __align__(16) uint16_t g_wth[DOUT * DIN];        // W^T hi bf16 [n][k]
__device__ __align__(16) uint16_t g_wtl[DOUT * DIN];        // W^T lo bf16
__device__ __align__(16) uint16_t g_xsth[DOUT * NTOK];      // (e2*xp)^T hi bf16 [c][token]
__device__ __align__(16) uint16_t g_xstl[DOUT * NTOK];      // (e2*xp)^T lo bf16
__device__ __align__(16) uint16_t g_adjbf[B_ * S_ * S_];    // valid adjacency bf16 [b][i][j]

// ---------------------------- helpers ----------------------------
__device__ __forceinline__ uint32_t smem_u32(const void* p) {
    uint32_t a;
    asm("{ .reg .u64 t; cvta.to.shared.u64 t, %1; cvt.u32.u64 %0, t; }" : "=r"(a) : "l"(p));
    return a;
}
__device__ __forceinline__ uint32_t swz(uint32_t off) { return off ^ ((off >> 3) & 0x70); }

__device__ __forceinline__ void cpasync16(uint32_t smem, const void* gmem) {
    asm volatile("cp.async.cg.shared.global [%0], [%1], 16;" :: "r"(smem), "l"(gmem));
}
__device__ __forceinline__ void cp_commit() {
    asm volatile("cp.async.commit_group;" ::: "memory");
}
template <int N>
__device__ __forceinline__ void cp_wait() {
    asm volatile("cp.async.wait_group %0;" :: "n"(N) : "memory");
}
__device__ __forceinline__ void ldsm4(uint32_t& r0, uint32_t& r1, uint32_t& r2, uint32_t& r3,
                                      uint32_t addr) {
    asm volatile("ldmatrix.sync.aligned.m8n8.x4.shared.b16 {%0,%1,%2,%3}, [%4];"
                 : "=r"(r0), "=r"(r1), "=r"(r2), "=r"(r3) : "r"(addr));
}
__device__ __forceinline__ void mma_bf16(float* c, const uint32_t* a, uint32_t b0, uint32_t b1) {
    asm volatile(
        "mma.sync.aligned.m16n8k16.row.col.f32.bf16.bf16.f32 "
        "{%0,%1,%2,%3}, {%4,%5,%6,%7}, {%8,%9}, {%0,%1,%2,%3};"
        : "+f"(c[0]), "+f"(c[1]), "+f"(c[2]), "+f"(c[3])
        : "r"(a[0]), "r"(a[1]), "r"(a[2]), "r"(a[3]), "r"(b0), "r"(b1));
}
__device__ __forceinline__ uint16_t bf16_bits(float f) {
    __nv_bfloat16 h = __float2bfloat16_rn(f);
    return *(uint16_t*)&h;
}
__device__ __forceinline__ float bf16_val(uint16_t b) {
    __nv_bfloat16 h = *(__nv_bfloat16*)&b;
    return __bfloat162float(h);
}
__device__ __forceinline__ void split_bf16(float x, uint16_t& hb, uint16_t& lb) {
    hb = bf16_bits(x);
    lb = bf16_bits(x - bf16_val(hb));
}
__device__ __forceinline__ void split2(float x0, float x1, uint32_t& hi, uint32_t& lo) {
    uint16_t h0, l0, h1, l1;
    split_bf16(x0, h0, l0);
    split_bf16(x1, h1, l1);
    hi = (uint32_t)h0 | ((uint32_t)h1 << 16);
    lo = (uint32_t)l0 | ((uint32_t)l1 << 16);
}

// ============================================================================
// Pre-pass 1: x -> hi/lo bf16
// ============================================================================
__global__ __launch_bounds__(256) void xsplit_in(const float* __restrict__ src) {
    size_t base = ((size_t)blockIdx.x * 256 + threadIdx.x) * 8;
    float4 v0 = *(const float4*)(src + base);
    float4 v1 = *(const float4*)(src + base + 4);
    uint32_t h0, l0, h1, l1, h2, l2, h3, l3;
    split2(v0.x, v0.y, h0, l0);
    split2(v0.z, v0.w, h1, l1);
    split2(v1.x, v1.y, h2, l2);
    split2(v1.z, v1.w, h3, l3);
    *(uint4*)(g_xh + base) = make_uint4(h0, h1, h2, h3);
    *(uint4*)(g_xl + base) = make_uint4(l0, l1, l2, l3);
}

// ============================================================================
// Pre-pass 2: W [k][n] -> W^T hi/lo bf16 [n][k]
// ============================================================================
__global__ __launch_bounds__(256) void wsplit(const float* __restrict__ W) {
    __shared__ float tile[32][33];
    int tx = threadIdx.x, ty = threadIdx.y;
    int n0 = blockIdx.x * 32, k0 = blockIdx.y * 32;
#pragma unroll
    for (int i = 0; i < 4; i++)
        tile[ty + i * 8][tx] = W[(size_t)(k0 + ty + i * 8) * DOUT + n0 + tx];
    __syncthreads();
#pragma unroll
    for (int i = 0; i < 4; i++) {
        int n = n0 + ty + i * 8, k = k0 + tx;
        float v = tile[tx][ty + i * 8];
        uint16_t h, l;
        split_bf16(v, h, l);
        g_wth[(size_t)n * DIN + k] = h;
        g_wtl[(size_t)n * DIN + k] = l;
    }
}

// ============================================================================
// Kernel 3: projection GEMM, BM=128 BN=256 BK=64, 512 thr, 2-stage cp.async
// ============================================================================
#define PROJ_STAGE 98304          // A hi/lo 16K+16K, B hi/lo 32K+32K
#define PROJ_SMEM (2 * PROJ_STAGE + 1024)
__global__ __launch_bounds__(512) void proj_mma() {
    extern __shared__ char dsm[];
    uint32_t sb = (smem_u32(dsm) + 1023) & ~1023u;

    int tid = threadIdx.x, lane = tid & 31, wid = tid >> 5;
    int wm = wid & 3, wn = wid >> 2;  // 4 x 4 warps, each 32m x 64n
    int m_base = blockIdx.y * 128, n_base = blockIdx.x * 256;

    int srow = tid >> 3, skg = tid & 7;  // srow 0..63, skg 0..7

    auto stage = [&](int ck, int s) {
        uint32_t base = sb + (uint32_t)s * PROJ_STAGE;
#pragma unroll
        for (int it = 0; it < 2; it++) {  // A: 128 rows
            int row = srow + it * 64;
            uint32_t so = swz((uint32_t)(row * 128 + skg * 16));
            size_t ga = (size_t)(m_base + row) * DIN + ck * 64 + skg * 8;
            cpasync16(base + so, g_xh + ga);
            cpasync16(base + 16384 + so, g_xl + ga);
        }
#pragma unroll
        for (int it = 0; it < 4; it++) {  // B: 256 rows
            int row = srow + it * 64;
            uint32_t so = swz((uint32_t)(row * 128 + skg * 16));
            size_t gb = (size_t)(n_base + row) * DIN + ck * 64 + skg * 8;
            cpasync16(base + 32768 + so, g_wth + gb);
            cpasync16(base + 65536 + so, g_wtl + gb);
        }
        cp_commit();
    };

    float acc[2][8][4] = {};

    stage(0, 0);
    for (int ck = 0; ck < 16; ck++) {
        if (ck + 1 < 16) {
            stage(ck + 1, (ck + 1) & 1);
            cp_wait<1>();
        } else {
            cp_wait<0>();
        }
        __syncthreads();
        uint32_t AH = sb + (uint32_t)(ck & 1) * PROJ_STAGE;
        uint32_t AL = AH + 16384, BH = AH + 32768, BL = AH + 65536;
#pragma unroll
        for (int ks = 0; ks < 4; ks++) {
            uint32_t ah[2][4], al[2][4];
#pragma unroll
            for (int mt = 0; mt < 2; mt++) {
                int r = wm * 32 + mt * 16 + (lane & 15);
                int kb = ks * 32 + (lane >> 4) * 16;
                uint32_t off = swz((uint32_t)(r * 128 + kb));
                ldsm4(ah[mt][0], ah[mt][1], ah[mt][2], ah[mt][3], AH + off);
                ldsm4(al[mt][0], al[mt][1], al[mt][2], al[mt][3], AL + off);
            }
#pragma unroll
            for (int nq = 0; nq < 4; nq++) {
                int r = wn * 64 + nq * 16 + (lane & 7) + ((lane >> 4) & 1) * 8;
                int kb = ks * 32 + ((lane >> 3) & 1) * 16;
                uint32_t off = swz((uint32_t)(r * 128 + kb));
                uint32_t bh[4], bl[4];
                ldsm4(bh[0], bh[1], bh[2], bh[3], BH + off);
                ldsm4(bl[0], bl[1], bl[2], bl[3], BL + off);
#pragma unroll
                for (int mt = 0; mt < 2; mt++) {
                    mma_bf16(acc[mt][nq * 2],     ah[mt], bh[0], bh[1]);
                    mma_bf16(acc[mt][nq * 2],     ah[mt], bl[0], bl[1]);
                    mma_bf16(acc[mt][nq * 2],     al[mt], bh[0], bh[1]);
                    mma_bf16(acc[mt][nq * 2 + 1], ah[mt], bh[2], bh[3]);
                    mma_bf16(acc[mt][nq * 2 + 1], ah[mt], bl[2], bl[3]);
                    mma_bf16(acc[mt][nq * 2 + 1], al[mt], bh[2], bh[3]);
                }
            }
        }
        __syncthreads();
    }
#pragma unroll
    for (int mt = 0; mt < 2; mt++)
#pragma unroll
        for (int nt = 0; nt < 8; nt++) {
            int r = m_base + wm * 32 + mt * 16 + (lane >> 2);
            int c = n_base + wn * 64 + nt * 8 + (lane & 3) * 2;
            float* a4 = acc[mt][nt];
            *(float2*)(g_xp + (size_t)r * DOUT + c) = make_float2(a4[0], a4[1]);
            *(float2*)(g_xp + (size_t)(r + 8) * DOUT + c) = make_float2(a4[2], a4[3]);
        }
}

// ============================================================================
// Kernel 4: fused s2 + max + exp + mask  (block per (b,h), 512 threads)
// ============================================================================
__global__ __launch_bounds__(512) void s2exp_kernel(const float* __restrict__ attw,
                                                    const float* __restrict__ mask) {
    __shared__ float s2s[S_];
    __shared__ float red[16];
    int bh = blockIdx.x;
    int b = bh >> 3, h = bh & 7;
    int tid = threadIdx.x, wid = tid >> 5, lane = tid & 31;
    float4 wv = *(const float4*)(attw + DATT + lane * 4);
#pragma unroll 1
    for (int t = wid; t < S_; t += 16) {
        float4 xv = *(const float4*)(g_xp + (size_t)(b * S_ + t) * DOUT + h * DATT + lane * 4);
        float s = xv.x * wv.x + xv.y * wv.y + xv.z * wv.z + xv.w * wv.w;
#pragma unroll
        for (int o = 16; o; o >>= 1) s += __shfl_xor_sync(0xFFFFFFFFu, s, o);
        if (lane == 0) s2s[t] = s;
    }
    __syncthreads();
    float v = s2s[tid];
    float m = v;
#pragma unroll
    for (int o = 16; o; o >>= 1) m = fmaxf(m, __shfl_xor_sync(0xFFFFFFFFu, m, o));
    if (lane == 0) red[wid] = m;
    __syncthreads();
    if (wid == 0) {
        float t = (lane < 16) ? red[lane] : -INFINITY;
#pragma unroll
        for (int o = 8; o; o >>= 1) t = fmaxf(t, __shfl_xor_sync(0xFFFFFFFFu, t, o));
        if (lane == 0) red[0] = t;
    }
    __syncthreads();
    m = red[0];
    float mj = mask[b * S_ + tid] > 0.f ? 1.f : 0.f;
    g_e2[(size_t)bh * S_ + tid] = mj * expf(v - m);
}

// ============================================================================
// Kernel 5: colsum[b,c] = sum_j xp[b,j,c]
// ============================================================================
__global__ __launch_bounds__(256) void colsum_kernel() {
    int idx = blockIdx.x * 256 + threadIdx.x;
    int b = idx >> 10, c = idx & 1023;
    const float* p = g_xp + (size_t)b * S_ * DOUT + c;
    float s = 0.f;
    for (int j = 0; j < S_; j++) s += p[(size_t)j * DOUT];
    g_colsum[idx] = s;
}

// ============================================================================
// Pre-pass 6: adjbf[b][i][j] = (adj>0 && mask_i>0) ? 1.0bf16 : 0
// ============================================================================
__global__ __launch_bounds__(256) void adjbf_kernel(const int* __restrict__ adj,
                                                    const float* __restrict__ mask) {
    size_t base = ((size_t)blockIdx.x * 256 + threadIdx.x) * 8;
    int bi = (int)(base >> 9);
    uint32_t one = (mask[bi] > 0.f) ? 0x3F80u : 0u;
    int4 a0 = *(const int4*)(adj + base);
    int4 a1 = *(const int4*)(adj + base + 4);
    uint32_t p0 = ((a0.x > 0) ? one : 0u) | (((a0.y > 0) ? one : 0u) << 16);
    uint32_t p1 = ((a0.z > 0) ? one : 0u) | (((a0.w > 0) ? one : 0u) << 16);
    uint32_t p2 = ((a1.x > 0) ? one : 0u) | (((a1.y > 0) ? one : 0u) << 16);
    uint32_t p3 = ((a1.z > 0) ? one : 0u) | (((a1.w > 0) ? one : 0u) << 16);
    *(uint4*)(g_adjbf + base) = make_uint4(p0, p1, p2, p3);
}

// ============================================================================
// Pre-pass 7: xsT[c][token] = split(e2[b,h(c),j] * xp[token][c])
// ============================================================================
__global__ __launch_bounds__(256) void xsplit_s() {
    __shared__ float tile[32][33];
    int tx = threadIdx.x, ty = threadIdx.y;
    int j0 = blockIdx.x * 32, c0 = blockIdx.y * 32;
#pragma unroll
    for (int i = 0; i < 4; i++)
        tile[ty + i * 8][tx] = g_xp[(size_t)(j0 + ty + i * 8) * DOUT + c0 + tx];
    __syncthreads();
#pragma unroll
    for (int i = 0; i < 4; i++) {
        int c = c0 + ty + i * 8;
        int j = j0 + tx;
        int b = j >> 9, h = c >> 7;
        float e = g_e2[(size_t)(b * H_ + h) * S_ + (j & 511)];
        float v = tile[tx][ty + i * 8] * e;
        uint16_t hb, lb;
        split_bf16(v, hb, lb);
        g_xsth[(size_t)c * NTOK + j] = hb;
        g_xstl[(size_t)c * NTOK + j] = lb;
    }
}

// ============================================================================
// Kernel 8: attention GEMM + in-MMA denominator + fused normalize
//   numerator: acc += adjbf[i][j] * xs_{hi,lo}[c][j]
//   denominator: extra n=8 MMA with B cols {e2_hi, e2_lo, 0...} -> acc_d
// ============================================================================
#define ATT_STAGE 49152
#define ATT_SMEM (2048 + 2 * ATT_STAGE + 1024)
__global__ __launch_bounds__(256) void att_mma(float* __restrict__ out) {
    extern __shared__ char dsm[];
    uint32_t sb = (smem_u32(dsm) + 1023) & ~1023u;
    uint32_t E2H = sb, E2L = sb + 1024;
    uint32_t stage0 = sb + 2048;

    int tid = threadIdx.x, lane = tid & 31, wid = tid >> 5;
    int wm = wid & 3, wn = wid >> 2;
    int h = blockIdx.x, i0 = blockIdx.y * 128, b = blockIdx.z;
    int c0 = h * DATT;

    // stage masked e2 split (bf16) into smem: 512 values
    {
        const float* e2p = g_e2 + (size_t)(b * H_ + h) * S_;
        for (int t = tid; t < S_; t += 256) {
            uint16_t hb, lb;
            split_bf16(e2p[t], hb, lb);
            *(uint16_t*)(dsm + (E2H - smem_u32(dsm)) + t * 2) = hb;
            *(uint16_t*)(dsm + (E2L - smem_u32(dsm)) + t * 2) = lb;
        }
    }

    int srow = tid >> 3, skg = tid & 7;

    auto stage = [&](int ck, int s) {
        uint32_t base = stage0 + (uint32_t)s * ATT_STAGE;
#pragma unroll
        for (int it = 0; it < 4; it++) {
            int row = srow + it * 32;
            uint32_t so = swz((uint32_t)(row * 128 + skg * 16));
            size_t ga = (size_t)(b * S_ + i0 + row) * S_ + ck * 64 + skg * 8;
            cpasync16(base + so, g_adjbf + ga);
            size_t gb = (size_t)(c0 + row) * NTOK + b * S_ + ck * 64 + skg * 8;
            cpasync16(base + 16384 + so, g_xsth + gb);
            cpasync16(base + 32768 + so, g_xstl + gb);
        }
        cp_commit();
    };

    float acc[2][8][4] = {};
    float acc_d[2][4] = {};
    int qq = lane & 3, nn = lane >> 2;

    stage(0, 0);
    for (int kc = 0; kc < 8; kc++) {
        if (kc + 1 < 8) {
            stage(kc + 1, (kc + 1) & 1);
            cp_wait<1>();
        } else {
            cp_wait<0>();
        }
        __syncthreads();
        uint32_t AD = stage0 + (uint32_t)(kc & 1) * ATT_STAGE;
        uint32_t BH = AD + 16384, BL = AD + 32768;
#pragma unroll
        for (int ks = 0; ks < 4; ks++) {
            uint32_t ad[2][4];
#pragma unroll
            for (int mt = 0; mt < 2; mt++) {
                int r = wm * 32 + mt * 16 + (lane & 15);
                int kb = ks * 32 + (lane >> 4) * 16;
                ldsm4(ad[mt][0], ad[mt][1], ad[mt][2], ad[mt][3],
                      AD + swz((uint32_t)(r * 128 + kb)));
            }
            // denominator fragment: cols {e2_hi, e2_lo, 0,...}
            {
                int jb = kc * 64 + ks * 16 + 2 * qq;
                uint32_t v0 = 0, v1 = 0;
                if (nn == 0) {
                    asm volatile("ld.shared.b32 %0, [%1];" : "=r"(v0) : "r"(E2H + jb * 2));
                    asm volatile("ld.shared.b32 %0, [%1];" : "=r"(v1) : "r"(E2H + (jb + 8) * 2));
                } else if (nn == 1) {
                    asm volatile("ld.shared.b32 %0, [%1];" : "=r"(v0) : "r"(E2L + jb * 2));
                    asm volatile("ld.shared.b32 %0, [%1];" : "=r"(v1) : "r"(E2L + (jb + 8) * 2));
                }
#pragma unroll
                for (int mt = 0; mt < 2; mt++)
                    mma_bf16(acc_d[mt], ad[mt], v0, v1);
            }
#pragma unroll
            for (int nq = 0; nq < 4; nq++) {
                int r = wn * 64 + nq * 16 + (lane & 7) + ((lane >> 4) & 1) * 8;
                int kb = ks * 32 + ((lane >> 3) & 1) * 16;
                uint32_t off = swz((uint32_t)(r * 128 + kb));
                uint32_t bh[4], bl[4];
                ldsm4(bh[0], bh[1], bh[2], bh[3], BH + off);
                ldsm4(bl[0], bl[1], bl[2], bl[3], BL + off);
#pragma unroll
                for (int mt = 0; mt < 2; mt++) {
                    mma_bf16(acc[mt][nq * 2],     ad[mt], bh[0], bh[1]);
                    mma_bf16(acc[mt][nq * 2],     ad[mt], bl[0], bl[1]);
                    mma_bf16(acc[mt][nq * 2 + 1], ad[mt], bh[2], bh[3]);
                    mma_bf16(acc[mt][nq * 2 + 1], ad[mt], bl[2], bl[3]);
                }
            }
        }
        __syncthreads();
    }

    // epilogue: denom from acc_d (cols 0+1 held by lane%4==0), normalize + fallback
    const float* cs = g_colsum + (b << 10);
#pragma unroll
    for (int mt = 0; mt < 2; mt++) {
        int r0 = i0 + wm * 32 + mt * 16 + (lane >> 2);
        float den0 = acc_d[mt][0] + acc_d[mt][1];
        float den1 = acc_d[mt][2] + acc_d[mt][3];
        float d0 = __shfl_sync(0xFFFFFFFFu, den0, lane & 28);
        float d1 = __shfl_sync(0xFFFFFFFFu, den1, lane & 28);
        float q0 = (d0 > 0.f) ? (1.0f / d0) : 0.f;
        float q1 = (d1 > 0.f) ? (1.0f / d1) : 0.f;
#pragma unroll
        for (int nt = 0; nt < 8; nt++) {
            int c = c0 + wn * 64 + nt * 8 + (lane & 3) * 2;
            float* a4 = acc[mt][nt];
            float2 o0, o1;
            if (d0 > 0.f) { o0 = make_float2(a4[0] * q0, a4[1] * q0); }
            else {
                float2 f = *(const float2*)(cs + c);
                o0 = make_float2(f.x * (1.0f / S_), f.y * (1.0f / S_));
            }
            if (d1 > 0.f) { o1 = make_float2(a4[2] * q1, a4[3] * q1); }
            else {
                float2 f = *(const float2*)(cs + c);
                o1 = make_float2(f.x * (1.0f / S_), f.y * (1.0f / S_));
            }
            *(float2*)(out + (size_t)(b * S_ + r0) * DOUT + c) = o0;
            *(float2*)(out + (size_t)(b * S_ + r0 + 8) * DOUT + c) = o1;
        }
    }
}

// ============================================================================
extern "C" void kernel_launch(void* const* d_in, const int* in_sizes, int n_in,
                              void* d_out, int out_size) {
    const float* x    = (const float*)d_in[0];
    const float* mask = (const float*)d_in[1];
    const int*   adj  = (const int*)d_in[2];
    const float* W    = (const float*)d_in[3];
    const float* attw = (const float*)d_in[4];
    float* out = (float*)d_out;

    cudaFuncSetAttribute(proj_mma, cudaFuncAttributeMaxDynamicSharedMemorySize, PROJ_SMEM);
    cudaFuncSetAttribute(att_mma, cudaFuncAttributeMaxDynamicSharedMemorySize, ATT_SMEM);

    xsplit_in<<<(NTOK * DIN) / (256 * 8), 256>>>(x);
    wsplit<<<dim3(DOUT / 32, DIN / 32), dim3(32, 8)>>>(W);
    adjbf_kernel<<<(B_ * S_ * S_) / (256 * 8), 256>>>(adj, mask);
    proj_mma<<<dim3(DOUT / 256, NTOK / 128), 512, PROJ_SMEM>>>();
    s2exp_kernel<<<B_ * H_, 512>>>(attw, mask);
    colsum_kernel<<<(B_ * DOUT) / 256, 256>>>();
    xsplit_s<<<dim3(NTOK / 32, DOUT / 32), dim3(32, 8)>>>();
    att_mma<<<dim3(H_, S_ / 128, B_), 256, ATT_SMEM>>>(out);
}

// round 7
// speedup vs baseline: 1.3001x; 1.3001x over previous
#include <cuda_runtime.h>
#include <cuda_fp16.h>
#include <math.h>
#include <stdint.h>

#define B_   8
#define S_   512
#define DIN  1024
#define DOUT 1024
#define H_   8
#define DATT 128
#define NTOK (B_ * S_)   // 4096

// ---------------- device scratch (no allocation allowed) ----------------
__device__ __align__(16) float    g_xp[NTOK * DOUT];        // projected x [token][chan]
__device__ __align__(16) float    g_e2[B_ * H_ * S_];       // masked exp(s2 - max)
__device__ __align__(16) float    g_colsum[B_ * DOUT];      // column sums (fallback)
__device__ __align__(16) uint16_t g_xh[NTOK * DIN];         // x hi fp16
__device__ __align__(16) uint16_t g_xl[NTOK * DIN];         // x lo fp16
__device__ __align__(16) uint16_t g_wt[DOUT * DIN];         // W^T fp16 [n][k]
__device__ __align__(16) uint16_t g_xst[DOUT * NTOK];       // (e2*xp)^T fp16 [c][token]
__device__ __align__(16) uint16_t g_adjf[B_ * S_ * S_];     // valid adjacency fp16 [b][i][j]

// ---------------------------- helpers ----------------------------
__device__ __forceinline__ uint32_t smem_u32(const void* p) {
    uint32_t a;
    asm("{ .reg .u64 t; cvta.to.shared.u64 t, %1; cvt.u32.u64 %0, t; }" : "=r"(a) : "l"(p));
    return a;
}
__device__ __forceinline__ uint32_t swz(uint32_t off) { return off ^ ((off >> 3) & 0x70); }

__device__ __forceinline__ void cpasync16(uint32_t smem, const void* gmem) {
    asm volatile("cp.async.cg.shared.global [%0], [%1], 16;" :: "r"(smem), "l"(gmem));
}
__device__ __forceinline__ void cp_commit() {
    asm volatile("cp.async.commit_group;" ::: "memory");
}
template <int N>
__device__ __forceinline__ void cp_wait() {
    asm volatile("cp.async.wait_group %0;" :: "n"(N) : "memory");
}
__device__ __forceinline__ void ldsm4(uint32_t& r0, uint32_t& r1, uint32_t& r2, uint32_t& r3,
                                      uint32_t addr) {
    asm volatile("ldmatrix.sync.aligned.m8n8.x4.shared.b16 {%0,%1,%2,%3}, [%4];"
                 : "=r"(r0), "=r"(r1), "=r"(r2), "=r"(r3) : "r"(addr));
}
__device__ __forceinline__ void mma_fp16(float* c, const uint32_t* a, uint32_t b0, uint32_t b1) {
    asm volatile(
        "mma.sync.aligned.m16n8k16.row.col.f32.f16.f16.f32 "
        "{%0,%1,%2,%3}, {%4,%5,%6,%7}, {%8,%9}, {%0,%1,%2,%3};"
        : "+f"(c[0]), "+f"(c[1]), "+f"(c[2]), "+f"(c[3])
        : "r"(a[0]), "r"(a[1]), "r"(a[2]), "r"(a[3]), "r"(b0), "r"(b1));
}
__device__ __forceinline__ uint16_t h_bits(float f) {
    __half h = __float2half_rn(f);
    return *(uint16_t*)&h;
}
__device__ __forceinline__ float h_val(uint16_t b) {
    __half h = *(__half*)&b;
    return __half2float(h);
}
__device__ __forceinline__ void split_fp16(float x, uint16_t& hb, uint16_t& lb) {
    hb = h_bits(x);
    lb = h_bits(x - h_val(hb));
}
__device__ __forceinline__ void split2(float x0, float x1, uint32_t& hi, uint32_t& lo) {
    uint16_t h0, l0, h1, l1;
    split_fp16(x0, h0, l0);
    split_fp16(x1, h1, l1);
    hi = (uint32_t)h0 | ((uint32_t)h1 << 16);
    lo = (uint32_t)l0 | ((uint32_t)l1 << 16);
}

// ============================================================================
// Pre-pass 1: x -> hi/lo fp16
// ============================================================================
__global__ __launch_bounds__(256) void xsplit_in(const float* __restrict__ src) {
    size_t base = ((size_t)blockIdx.x * 256 + threadIdx.x) * 8;
    float4 v0 = *(const float4*)(src + base);
    float4 v1 = *(const float4*)(src + base + 4);
    uint32_t h0, l0, h1, l1, h2, l2, h3, l3;
    split2(v0.x, v0.y, h0, l0);
    split2(v0.z, v0.w, h1, l1);
    split2(v1.x, v1.y, h2, l2);
    split2(v1.z, v1.w, h3, l3);
    *(uint4*)(g_xh + base) = make_uint4(h0, h1, h2, h3);
    *(uint4*)(g_xl + base) = make_uint4(l0, l1, l2, l3);
}

// ============================================================================
// Pre-pass 2: W [k][n] -> W^T fp16 [n][k] (transpose + single round)
// ============================================================================
__global__ __launch_bounds__(256) void wsplit(const float* __restrict__ W) {
    __shared__ float tile[32][33];
    int tx = threadIdx.x, ty = threadIdx.y;
    int n0 = blockIdx.x * 32, k0 = blockIdx.y * 32;
#pragma unroll
    for (int i = 0; i < 4; i++)
        tile[ty + i * 8][tx] = W[(size_t)(k0 + ty + i * 8) * DOUT + n0 + tx];
    __syncthreads();
#pragma unroll
    for (int i = 0; i < 4; i++) {
        int n = n0 + ty + i * 8, k = k0 + tx;
        g_wt[(size_t)n * DIN + k] = h_bits(tile[tx][ty + i * 8]);
    }
}

// ============================================================================
// Kernel 3: projection GEMM, BM=128 BN=256 BK=64, 512 thr, 2-stage cp.async
//   acc = (x_hi + x_lo) * w  -> 2 fp16 MMAs per tile pair
// ============================================================================
#define PROJ_STAGE 65536          // A hi 16K + A lo 16K + B 32K
#define PROJ_SMEM (2 * PROJ_STAGE + 1024)
__global__ __launch_bounds__(512) void proj_mma() {
    extern __shared__ char dsm[];
    uint32_t sb = (smem_u32(dsm) + 1023) & ~1023u;

    int tid = threadIdx.x, lane = tid & 31, wid = tid >> 5;
    int wm = wid & 3, wn = wid >> 2;  // 4 x 4 warps, each 32m x 64n
    int m_base = blockIdx.y * 128, n_base = blockIdx.x * 256;

    int srow = tid >> 3, skg = tid & 7;  // srow 0..63, skg 0..7

    auto stage = [&](int ck, int s) {
        uint32_t base = sb + (uint32_t)s * PROJ_STAGE;
#pragma unroll
        for (int it = 0; it < 2; it++) {  // A: 128 rows, hi+lo
            int row = srow + it * 64;
            uint32_t so = swz((uint32_t)(row * 128 + skg * 16));
            size_t ga = (size_t)(m_base + row) * DIN + ck * 64 + skg * 8;
            cpasync16(base + so, g_xh + ga);
            cpasync16(base + 16384 + so, g_xl + ga);
        }
#pragma unroll
        for (int it = 0; it < 4; it++) {  // B: 256 rows, single
            int row = srow + it * 64;
            uint32_t so = swz((uint32_t)(row * 128 + skg * 16));
            size_t gb = (size_t)(n_base + row) * DIN + ck * 64 + skg * 8;
            cpasync16(base + 32768 + so, g_wt + gb);
        }
        cp_commit();
    };

    float acc[2][8][4] = {};

    stage(0, 0);
    for (int ck = 0; ck < 16; ck++) {
        if (ck + 1 < 16) {
            stage(ck + 1, (ck + 1) & 1);
            cp_wait<1>();
        } else {
            cp_wait<0>();
        }
        __syncthreads();
        uint32_t AH = sb + (uint32_t)(ck & 1) * PROJ_STAGE;
        uint32_t AL = AH + 16384, BS = AH + 32768;
#pragma unroll
        for (int ks = 0; ks < 4; ks++) {
            uint32_t ah[2][4], al[2][4];
#pragma unroll
            for (int mt = 0; mt < 2; mt++) {
                int r = wm * 32 + mt * 16 + (lane & 15);
                int kb = ks * 32 + (lane >> 4) * 16;
                uint32_t off = swz((uint32_t)(r * 128 + kb));
                ldsm4(ah[mt][0], ah[mt][1], ah[mt][2], ah[mt][3], AH + off);
                ldsm4(al[mt][0], al[mt][1], al[mt][2], al[mt][3], AL + off);
            }
#pragma unroll
            for (int nq = 0; nq < 4; nq++) {
                int r = wn * 64 + nq * 16 + (lane & 7) + ((lane >> 4) & 1) * 8;
                int kb = ks * 32 + ((lane >> 3) & 1) * 16;
                uint32_t off = swz((uint32_t)(r * 128 + kb));
                uint32_t bs[4];
                ldsm4(bs[0], bs[1], bs[2], bs[3], BS + off);
#pragma unroll
                for (int mt = 0; mt < 2; mt++) {
                    mma_fp16(acc[mt][nq * 2],     ah[mt], bs[0], bs[1]);
                    mma_fp16(acc[mt][nq * 2],     al[mt], bs[0], bs[1]);
                    mma_fp16(acc[mt][nq * 2 + 1], ah[mt], bs[2], bs[3]);
                    mma_fp16(acc[mt][nq * 2 + 1], al[mt], bs[2], bs[3]);
                }
            }
        }
        __syncthreads();
    }
#pragma unroll
    for (int mt = 0; mt < 2; mt++)
#pragma unroll
        for (int nt = 0; nt < 8; nt++) {
            int r = m_base + wm * 32 + mt * 16 + (lane >> 2);
            int c = n_base + wn * 64 + nt * 8 + (lane & 3) * 2;
            float* a4 = acc[mt][nt];
            *(float2*)(g_xp + (size_t)r * DOUT + c) = make_float2(a4[0], a4[1]);
            *(float2*)(g_xp + (size_t)(r + 8) * DOUT + c) = make_float2(a4[2], a4[3]);
        }
}

// ============================================================================
// Kernel 4: fused s2 + max + exp + mask  (block per (b,h), 512 threads)
// ============================================================================
__global__ __launch_bounds__(512) void s2exp_kernel(const float* __restrict__ attw,
                                                    const float* __restrict__ mask) {
    __shared__ float s2s[S_];
    __shared__ float red[16];
    int bh = blockIdx.x;
    int b = bh >> 3, h = bh & 7;
    int tid = threadIdx.x, wid = tid >> 5, lane = tid & 31;
    float4 wv = *(const float4*)(attw + DATT + lane * 4);
#pragma unroll 1
    for (int t = wid; t < S_; t += 16) {
        float4 xv = *(const float4*)(g_xp + (size_t)(b * S_ + t) * DOUT + h * DATT + lane * 4);
        float s = xv.x * wv.x + xv.y * wv.y + xv.z * wv.z + xv.w * wv.w;
#pragma unroll
        for (int o = 16; o; o >>= 1) s += __shfl_xor_sync(0xFFFFFFFFu, s, o);
        if (lane == 0) s2s[t] = s;
    }
    __syncthreads();
    float v = s2s[tid];
    float m = v;
#pragma unroll
    for (int o = 16; o; o >>= 1) m = fmaxf(m, __shfl_xor_sync(0xFFFFFFFFu, m, o));
    if (lane == 0) red[wid] = m;
    __syncthreads();
    if (wid == 0) {
        float t = (lane < 16) ? red[lane] : -INFINITY;
#pragma unroll
        for (int o = 8; o; o >>= 1) t = fmaxf(t, __shfl_xor_sync(0xFFFFFFFFu, t, o));
        if (lane == 0) red[0] = t;
    }
    __syncthreads();
    m = red[0];
    float mj = mask[b * S_ + tid] > 0.f ? 1.f : 0.f;
    g_e2[(size_t)bh * S_ + tid] = mj * expf(v - m);
}

// ============================================================================
// Kernel 5: colsum[b,c] = sum_j xp[b,j,c]
// ============================================================================
__global__ __launch_bounds__(256) void colsum_kernel() {
    int idx = blockIdx.x * 256 + threadIdx.x;
    int b = idx >> 10, c = idx & 1023;
    const float* p = g_xp + (size_t)b * S_ * DOUT + c;
    float s = 0.f;
    for (int j = 0; j < S_; j++) s += p[(size_t)j * DOUT];
    g_colsum[idx] = s;
}

// ============================================================================
// Pre-pass 6: adjf[b][i][j] = (adj>0 && mask_i>0) ? 1.0fp16 : 0
// ============================================================================
__global__ __launch_bounds__(256) void adjf_kernel(const int* __restrict__ adj,
                                                   const float* __restrict__ mask) {
    size_t base = ((size_t)blockIdx.x * 256 + threadIdx.x) * 8;
    int bi = (int)(base >> 9);
    uint32_t one = (mask[bi] > 0.f) ? 0x3C00u : 0u;   // fp16 1.0
    int4 a0 = *(const int4*)(adj + base);
    int4 a1 = *(const int4*)(adj + base + 4);
    uint32_t p0 = ((a0.x > 0) ? one : 0u) | (((a0.y > 0) ? one : 0u) << 16);
    uint32_t p1 = ((a0.z > 0) ? one : 0u) | (((a0.w > 0) ? one : 0u) << 16);
    uint32_t p2 = ((a1.x > 0) ? one : 0u) | (((a1.y > 0) ? one : 0u) << 16);
    uint32_t p3 = ((a1.z > 0) ? one : 0u) | (((a1.w > 0) ? one : 0u) << 16);
    *(uint4*)(g_adjf + base) = make_uint4(p0, p1, p2, p3);
}

// ============================================================================
// Pre-pass 7: xsT[c][token] = fp16(e2[b,h(c),j] * xp[token][c]) (transpose)
// ============================================================================
__global__ __launch_bounds__(256) void xsplit_s() {
    __shared__ float tile[32][33];
    int tx = threadIdx.x, ty = threadIdx.y;
    int j0 = blockIdx.x * 32, c0 = blockIdx.y * 32;
#pragma unroll
    for (int i = 0; i < 4; i++)
        tile[ty + i * 8][tx] = g_xp[(size_t)(j0 + ty + i * 8) * DOUT + c0 + tx];
    __syncthreads();
#pragma unroll
    for (int i = 0; i < 4; i++) {
        int c = c0 + ty + i * 8;
        int j = j0 + tx;
        int b = j >> 9, h = c >> 7;
        float e = g_e2[(size_t)(b * H_ + h) * S_ + (j & 511)];
        g_xst[(size_t)c * NTOK + j] = h_bits(tile[tx][ty + i * 8] * e);
    }
}

// ============================================================================
// Kernel 8: attention GEMM + in-MMA denominator + fused normalize
//   numerator: acc += adjf[i][j] * xst[c][j]     (1 fp16 MMA per tile)
//   denominator: extra n=8 MMA, B col0 = e2 fp16 -> acc_d
// ============================================================================
#define ATT_STAGE 32768           // adj 16K + B 16K
#define ATT_SMEM (1024 + 2 * ATT_STAGE + 1024)
__global__ __launch_bounds__(256) void att_mma(float* __restrict__ out) {
    extern __shared__ char dsm[];
    uint32_t sb = (smem_u32(dsm) + 1023) & ~1023u;
    uint32_t E2 = sb;
    uint32_t stage0 = sb + 1024;

    int tid = threadIdx.x, lane = tid & 31, wid = tid >> 5;
    int wm = wid & 3, wn = wid >> 2;
    int h = blockIdx.x, i0 = blockIdx.y * 128, b = blockIdx.z;
    int c0 = h * DATT;

    // stage masked e2 (fp16) into smem: 512 values
    {
        const float* e2p = g_e2 + (size_t)(b * H_ + h) * S_;
        for (int t = tid; t < S_; t += 256) {
            uint16_t hb = h_bits(e2p[t]);
            asm volatile("st.shared.b16 [%0], %1;" :: "r"(E2 + t * 2), "h"(hb));
        }
    }

    int srow = tid >> 3, skg = tid & 7;

    auto stage = [&](int ck, int s) {
        uint32_t base = stage0 + (uint32_t)s * ATT_STAGE;
#pragma unroll
        for (int it = 0; it < 4; it++) {
            int row = srow + it * 32;
            uint32_t so = swz((uint32_t)(row * 128 + skg * 16));
            size_t ga = (size_t)(b * S_ + i0 + row) * S_ + ck * 64 + skg * 8;
            cpasync16(base + so, g_adjf + ga);
            size_t gb = (size_t)(c0 + row) * NTOK + b * S_ + ck * 64 + skg * 8;
            cpasync16(base + 16384 + so, g_xst + gb);
        }
        cp_commit();
    };

    float acc[2][8][4] = {};
    float acc_d[2][4] = {};
    int qq = lane & 3, nn = lane >> 2;

    stage(0, 0);
    for (int kc = 0; kc < 8; kc++) {
        if (kc + 1 < 8) {
            stage(kc + 1, (kc + 1) & 1);
            cp_wait<1>();
        } else {
            cp_wait<0>();
        }
        __syncthreads();
        uint32_t AD = stage0 + (uint32_t)(kc & 1) * ATT_STAGE;
        uint32_t BS = AD + 16384;
#pragma unroll
        for (int ks = 0; ks < 4; ks++) {
            uint32_t ad[2][4];
#pragma unroll
            for (int mt = 0; mt < 2; mt++) {
                int r = wm * 32 + mt * 16 + (lane & 15);
                int kb = ks * 32 + (lane >> 4) * 16;
                ldsm4(ad[mt][0], ad[mt][1], ad[mt][2], ad[mt][3],
                      AD + swz((uint32_t)(r * 128 + kb)));
            }
            // denominator fragment: B col0 = e2, other cols 0
            {
                int jb = kc * 64 + ks * 16 + 2 * qq;
                uint32_t v0 = 0, v1 = 0;
                if (nn == 0) {
                    asm volatile("ld.shared.b32 %0, [%1];" : "=r"(v0) : "r"(E2 + jb * 2));
                    asm volatile("ld.shared.b32 %0, [%1];" : "=r"(v1) : "r"(E2 + (jb + 8) * 2));
                }
#pragma unroll
                for (int mt = 0; mt < 2; mt++)
                    mma_fp16(acc_d[mt], ad[mt], v0, v1);
            }
#pragma unroll
            for (int nq = 0; nq < 4; nq++) {
                int r = wn * 64 + nq * 16 + (lane & 7) + ((lane >> 4) & 1) * 8;
                int kb = ks * 32 + ((lane >> 3) & 1) * 16;
                uint32_t off = swz((uint32_t)(r * 128 + kb));
                uint32_t bs[4];
                ldsm4(bs[0], bs[1], bs[2], bs[3], BS + off);
#pragma unroll
                for (int mt = 0; mt < 2; mt++) {
                    mma_fp16(acc[mt][nq * 2],     ad[mt], bs[0], bs[1]);
                    mma_fp16(acc[mt][nq * 2 + 1], ad[mt], bs[2], bs[3]);
                }
            }
        }
        __syncthreads();
    }

    // epilogue: denom = col0 of acc_d (held by lane%4==0), normalize + fallback
    const float* cs = g_colsum + (b << 10);
#pragma unroll
    for (int mt = 0; mt < 2; mt++) {
        int r0 = i0 + wm * 32 + mt * 16 + (lane >> 2);
        float d0 = __shfl_sync(0xFFFFFFFFu, acc_d[mt][0], lane & 28);
        float d1 = __shfl_sync(0xFFFFFFFFu, acc_d[mt][2], lane & 28);
        float q0 = (d0 > 0.f) ? (1.0f / d0) : 0.f;
        float q1 = (d1 > 0.f) ? (1.0f / d1) : 0.f;
#pragma unroll
        for (int nt = 0; nt < 8; nt++) {
            int c = c0 + wn * 64 + nt * 8 + (lane & 3) * 2;
            float* a4 = acc[mt][nt];
            float2 o0, o1;
            if (d0 > 0.f) { o0 = make_float2(a4[0] * q0, a4[1] * q0); }
            else {
                float2 f = *(const float2*)(cs + c);
                o0 = make_float2(f.x * (1.0f / S_), f.y * (1.0f / S_));
            }
            if (d1 > 0.f) { o1 = make_float2(a4[2] * q1, a4[3] * q1); }
            else {
                float2 f = *(const float2*)(cs + c);
                o1 = make_float2(f.x * (1.0f / S_), f.y * (1.0f / S_));
            }
            *(float2*)(out + (size_t)(b * S_ + r0) * DOUT + c) = o0;
            *(float2*)(out + (size_t)(b * S_ + r0 + 8) * DOUT + c) = o1;
        }
    }
}

// ============================================================================
extern "C" void kernel_launch(void* const* d_in, const int* in_sizes, int n_in,
                              void* d_out, int out_size) {
    const float* x    = (const float*)d_in[0];
    const float* mask = (const float*)d_in[1];
    const int*   adj  = (const int*)d_in[2];
    const float* W    = (const float*)d_in[3];
    const float* attw = (const float*)d_in[4];
    float* out = (float*)d_out;

    cudaFuncSetAttribute(proj_mma, cudaFuncAttributeMaxDynamicSharedMemorySize, PROJ_SMEM);
    cudaFuncSetAttribute(att_mma, cudaFuncAttributeMaxDynamicSharedMemorySize, ATT_SMEM);

    xsplit_in<<<(NTOK * DIN) / (256 * 8), 256>>>(x);
    wsplit<<<dim3(DOUT / 32, DIN / 32), dim3(32, 8)>>>(W);
    adjf_kernel<<<(B_ * S_ * S_) / (256 * 8), 256>>>(adj, mask);
    proj_mma<<<dim3(DOUT / 256, NTOK / 128), 512, PROJ_SMEM>>>();
    s2exp_kernel<<<B_ * H_, 512>>>(attw, mask);
    colsum_kernel<<<(B_ * DOUT) / 256, 256>>>();
    xsplit_s<<<dim3(NTOK / 32, DOUT / 32), dim3(32, 8)>>>();
    att_mma<<<dim3(H_, S_ / 128, B_), 256, ATT_SMEM>>>(out);
}

// round 8
// speedup vs baseline: 1.5932x; 1.2254x over previous
#include <cuda_runtime.h>
#include <cuda_fp16.h>
#include <math.h>
#include <stdint.h>

#define B_   8
#define S_   512
#define DIN  1024
#define DOUT 1024
#define H_   8
#define DATT 128
#define NTOK (B_ * S_)   // 4096

// ---------------- device scratch (no allocation allowed) ----------------
__device__ __align__(16) float    g_xp[NTOK * DOUT];        // projected x [token][chan]
__device__ __align__(16) float    g_e2[B_ * H_ * S_];       // masked exp(s2 - max)
__device__ __align__(16) float    g_colsum[B_ * DOUT];      // column sums (fallback)
__device__ __align__(16) uint16_t g_xf[NTOK * DIN];         // x fp16
__device__ __align__(16) uint16_t g_wt[DOUT * DIN];         // W^T fp16 [n][k]
__device__ __align__(16) uint16_t g_xst[DOUT * NTOK];       // (e2*xp)^T fp16 [c][token]
__device__ __align__(16) uint16_t g_adjf[B_ * S_ * S_];     // valid adjacency fp16 [b][i][j]

// ---------------------------- helpers ----------------------------
__device__ __forceinline__ uint32_t smem_u32(const void* p) {
    uint32_t a;
    asm("{ .reg .u64 t; cvta.to.shared.u64 t, %1; cvt.u32.u64 %0, t; }" : "=r"(a) : "l"(p));
    return a;
}
__device__ __forceinline__ uint32_t swz(uint32_t off) { return off ^ ((off >> 3) & 0x70); }

__device__ __forceinline__ void cpasync16(uint32_t smem, const void* gmem) {
    asm volatile("cp.async.cg.shared.global [%0], [%1], 16;" :: "r"(smem), "l"(gmem));
}
__device__ __forceinline__ void cp_commit() {
    asm volatile("cp.async.commit_group;" ::: "memory");
}
template <int N>
__device__ __forceinline__ void cp_wait() {
    asm volatile("cp.async.wait_group %0;" :: "n"(N) : "memory");
}
__device__ __forceinline__ void ldsm4(uint32_t& r0, uint32_t& r1, uint32_t& r2, uint32_t& r3,
                                      uint32_t addr) {
    asm volatile("ldmatrix.sync.aligned.m8n8.x4.shared.b16 {%0,%1,%2,%3}, [%4];"
                 : "=r"(r0), "=r"(r1), "=r"(r2), "=r"(r3) : "r"(addr));
}
__device__ __forceinline__ void mma_fp16(float* c, const uint32_t* a, uint32_t b0, uint32_t b1) {
    asm volatile(
        "mma.sync.aligned.m16n8k16.row.col.f32.f16.f16.f32 "
        "{%0,%1,%2,%3}, {%4,%5,%6,%7}, {%8,%9}, {%0,%1,%2,%3};"
        : "+f"(c[0]), "+f"(c[1]), "+f"(c[2]), "+f"(c[3])
        : "r"(a[0]), "r"(a[1]), "r"(a[2]), "r"(a[3]), "r"(b0), "r"(b1));
}
__device__ __forceinline__ uint16_t h_bits(float f) {
    __half h = __float2half_rn(f);
    return *(uint16_t*)&h;
}
__device__ __forceinline__ uint32_t h2_bits(float x0, float x1) {
    return (uint32_t)h_bits(x0) | ((uint32_t)h_bits(x1) << 16);
}

// ============================================================================
// Pre-pass 1: x -> fp16
// ============================================================================
__global__ __launch_bounds__(256) void xcvt(const float* __restrict__ src) {
    size_t base = ((size_t)blockIdx.x * 256 + threadIdx.x) * 8;
    float4 v0 = *(const float4*)(src + base);
    float4 v1 = *(const float4*)(src + base + 4);
    *(uint4*)(g_xf + base) = make_uint4(h2_bits(v0.x, v0.y), h2_bits(v0.z, v0.w),
                                        h2_bits(v1.x, v1.y), h2_bits(v1.z, v1.w));
}

// ============================================================================
// Pre-pass 2: W [k][n] -> W^T fp16 [n][k] (transpose + single round)
// ============================================================================
__global__ __launch_bounds__(256) void wsplit(const float* __restrict__ W) {
    __shared__ float tile[32][33];
    int tx = threadIdx.x, ty = threadIdx.y;
    int n0 = blockIdx.x * 32, k0 = blockIdx.y * 32;
#pragma unroll
    for (int i = 0; i < 4; i++)
        tile[ty + i * 8][tx] = W[(size_t)(k0 + ty + i * 8) * DOUT + n0 + tx];
    __syncthreads();
#pragma unroll
    for (int i = 0; i < 4; i++) {
        int n = n0 + ty + i * 8, k = k0 + tx;
        g_wt[(size_t)n * DIN + k] = h_bits(tile[tx][ty + i * 8]);
    }
}

// ============================================================================
// Kernel 3: projection GEMM, BM=128 BN=256 BK=64, 512 thr, 2-stage cp.async
//   single fp16 x and W -> 1 MMA per tile
// ============================================================================
#define PROJ_STAGE 49152          // A 16K + B 32K
#define PROJ_SMEM (2 * PROJ_STAGE + 1024)
__global__ __launch_bounds__(512) void proj_mma() {
    extern __shared__ char dsm[];
    uint32_t sb = (smem_u32(dsm) + 1023) & ~1023u;

    int tid = threadIdx.x, lane = tid & 31, wid = tid >> 5;
    int wm = wid & 3, wn = wid >> 2;  // 4 x 4 warps, each 32m x 64n
    int m_base = blockIdx.y * 128, n_base = blockIdx.x * 256;

    int srow = tid >> 3, skg = tid & 7;  // srow 0..63, skg 0..7

    auto stage = [&](int ck, int s) {
        uint32_t base = sb + (uint32_t)s * PROJ_STAGE;
#pragma unroll
        for (int it = 0; it < 2; it++) {  // A: 128 rows
            int row = srow + it * 64;
            uint32_t so = swz((uint32_t)(row * 128 + skg * 16));
            size_t ga = (size_t)(m_base + row) * DIN + ck * 64 + skg * 8;
            cpasync16(base + so, g_xf + ga);
        }
#pragma unroll
        for (int it = 0; it < 4; it++) {  // B: 256 rows
            int row = srow + it * 64;
            uint32_t so = swz((uint32_t)(row * 128 + skg * 16));
            size_t gb = (size_t)(n_base + row) * DIN + ck * 64 + skg * 8;
            cpasync16(base + 16384 + so, g_wt + gb);
        }
        cp_commit();
    };

    float acc[2][8][4] = {};

    stage(0, 0);
    for (int ck = 0; ck < 16; ck++) {
        if (ck + 1 < 16) {
            stage(ck + 1, (ck + 1) & 1);
            cp_wait<1>();
        } else {
            cp_wait<0>();
        }
        __syncthreads();
        uint32_t AS = sb + (uint32_t)(ck & 1) * PROJ_STAGE;
        uint32_t BS = AS + 16384;
#pragma unroll
        for (int ks = 0; ks < 4; ks++) {
            uint32_t af[2][4];
#pragma unroll
            for (int mt = 0; mt < 2; mt++) {
                int r = wm * 32 + mt * 16 + (lane & 15);
                int kb = ks * 32 + (lane >> 4) * 16;
                uint32_t off = swz((uint32_t)(r * 128 + kb));
                ldsm4(af[mt][0], af[mt][1], af[mt][2], af[mt][3], AS + off);
            }
#pragma unroll
            for (int nq = 0; nq < 4; nq++) {
                int r = wn * 64 + nq * 16 + (lane & 7) + ((lane >> 4) & 1) * 8;
                int kb = ks * 32 + ((lane >> 3) & 1) * 16;
                uint32_t off = swz((uint32_t)(r * 128 + kb));
                uint32_t bs[4];
                ldsm4(bs[0], bs[1], bs[2], bs[3], BS + off);
#pragma unroll
                for (int mt = 0; mt < 2; mt++) {
                    mma_fp16(acc[mt][nq * 2],     af[mt], bs[0], bs[1]);
                    mma_fp16(acc[mt][nq * 2 + 1], af[mt], bs[2], bs[3]);
                }
            }
        }
        __syncthreads();
    }
#pragma unroll
    for (int mt = 0; mt < 2; mt++)
#pragma unroll
        for (int nt = 0; nt < 8; nt++) {
            int r = m_base + wm * 32 + mt * 16 + (lane >> 2);
            int c = n_base + wn * 64 + nt * 8 + (lane & 3) * 2;
            float* a4 = acc[mt][nt];
            *(float2*)(g_xp + (size_t)r * DOUT + c) = make_float2(a4[0], a4[1]);
            *(float2*)(g_xp + (size_t)(r + 8) * DOUT + c) = make_float2(a4[2], a4[3]);
        }
}

// ============================================================================
// Kernel 4: fused s2 + max + exp + mask  (block per (b,h), 512 threads)
// ============================================================================
__global__ __launch_bounds__(512) void s2exp_kernel(const float* __restrict__ attw,
                                                    const float* __restrict__ mask) {
    __shared__ float s2s[S_];
    __shared__ float red[16];
    int bh = blockIdx.x;
    int b = bh >> 3, h = bh & 7;
    int tid = threadIdx.x, wid = tid >> 5, lane = tid & 31;
    float4 wv = *(const float4*)(attw + DATT + lane * 4);
#pragma unroll 1
    for (int t = wid; t < S_; t += 16) {
        float4 xv = *(const float4*)(g_xp + (size_t)(b * S_ + t) * DOUT + h * DATT + lane * 4);
        float s = xv.x * wv.x + xv.y * wv.y + xv.z * wv.z + xv.w * wv.w;
#pragma unroll
        for (int o = 16; o; o >>= 1) s += __shfl_xor_sync(0xFFFFFFFFu, s, o);
        if (lane == 0) s2s[t] = s;
    }
    __syncthreads();
    float v = s2s[tid];
    float m = v;
#pragma unroll
    for (int o = 16; o; o >>= 1) m = fmaxf(m, __shfl_xor_sync(0xFFFFFFFFu, m, o));
    if (lane == 0) red[wid] = m;
    __syncthreads();
    if (wid == 0) {
        float t = (lane < 16) ? red[lane] : -INFINITY;
#pragma unroll
        for (int o = 8; o; o >>= 1) t = fmaxf(t, __shfl_xor_sync(0xFFFFFFFFu, t, o));
        if (lane == 0) red[0] = t;
    }
    __syncthreads();
    m = red[0];
    float mj = mask[b * S_ + tid] > 0.f ? 1.f : 0.f;
    g_e2[(size_t)bh * S_ + tid] = mj * expf(v - m);
}

// ============================================================================
// Kernel 5: colsum[b,c] = sum_j xp[b,j,c]
// ============================================================================
__global__ __launch_bounds__(256) void colsum_kernel() {
    int idx = blockIdx.x * 256 + threadIdx.x;
    int b = idx >> 10, c = idx & 1023;
    const float* p = g_xp + (size_t)b * S_ * DOUT + c;
    float s = 0.f;
    for (int j = 0; j < S_; j++) s += p[(size_t)j * DOUT];
    g_colsum[idx] = s;
}

// ============================================================================
// Pre-pass 6: adjf[b][i][j] = (adj>0 && mask_i>0) ? 1.0fp16 : 0
// ============================================================================
__global__ __launch_bounds__(256) void adjf_kernel(const int* __restrict__ adj,
                                                   const float* __restrict__ mask) {
    size_t base = ((size_t)blockIdx.x * 256 + threadIdx.x) * 8;
    int bi = (int)(base >> 9);
    uint32_t one = (mask[bi] > 0.f) ? 0x3C00u : 0u;   // fp16 1.0
    int4 a0 = *(const int4*)(adj + base);
    int4 a1 = *(const int4*)(adj + base + 4);
    uint32_t p0 = ((a0.x > 0) ? one : 0u) | (((a0.y > 0) ? one : 0u) << 16);
    uint32_t p1 = ((a0.z > 0) ? one : 0u) | (((a0.w > 0) ? one : 0u) << 16);
    uint32_t p2 = ((a1.x > 0) ? one : 0u) | (((a1.y > 0) ? one : 0u) << 16);
    uint32_t p3 = ((a1.z > 0) ? one : 0u) | (((a1.w > 0) ? one : 0u) << 16);
    *(uint4*)(g_adjf + base) = make_uint4(p0, p1, p2, p3);
}

// ============================================================================
// Pre-pass 7: xsT[c][token] = fp16(e2[b,h(c),j] * xp[token][c]) (transpose)
// ============================================================================
__global__ __launch_bounds__(256) void xsplit_s() {
    __shared__ float tile[32][33];
    int tx = threadIdx.x, ty = threadIdx.y;
    int j0 = blockIdx.x * 32, c0 = blockIdx.y * 32;
#pragma unroll
    for (int i = 0; i < 4; i++)
        tile[ty + i * 8][tx] = g_xp[(size_t)(j0 + ty + i * 8) * DOUT + c0 + tx];
    __syncthreads();
#pragma unroll
    for (int i = 0; i < 4; i++) {
        int c = c0 + ty + i * 8;
        int j = j0 + tx;
        int b = j >> 9, h = c >> 7;
        float e = g_e2[(size_t)(b * H_ + h) * S_ + (j & 511)];
        g_xst[(size_t)c * NTOK + j] = h_bits(tile[tx][ty + i * 8] * e);
    }
}

// ============================================================================
// Kernel 8: attention GEMM + in-MMA denominator + fused normalize
// ============================================================================
#define ATT_STAGE 32768           // adj 16K + B 16K
#define ATT_SMEM (1024 + 2 * ATT_STAGE + 1024)
__global__ __launch_bounds__(256) void att_mma(float* __restrict__ out) {
    extern __shared__ char dsm[];
    uint32_t sb = (smem_u32(dsm) + 1023) & ~1023u;
    uint32_t E2 = sb;
    uint32_t stage0 = sb + 1024;

    int tid = threadIdx.x, lane = tid & 31, wid = tid >> 5;
    int wm = wid & 3, wn = wid >> 2;
    int h = blockIdx.x, i0 = blockIdx.y * 128, b = blockIdx.z;
    int c0 = h * DATT;

    // stage masked e2 (fp16) into smem: 512 values
    {
        const float* e2p = g_e2 + (size_t)(b * H_ + h) * S_;
        for (int t = tid; t < S_; t += 256) {
            uint16_t hb = h_bits(e2p[t]);
            asm volatile("st.shared.b16 [%0], %1;" :: "r"(E2 + t * 2), "h"(hb));
        }
    }

    int srow = tid >> 3, skg = tid & 7;

    auto stage = [&](int ck, int s) {
        uint32_t base = stage0 + (uint32_t)s * ATT_STAGE;
#pragma unroll
        for (int it = 0; it < 4; it++) {
            int row = srow + it * 32;
            uint32_t so = swz((uint32_t)(row * 128 + skg * 16));
            size_t ga = (size_t)(b * S_ + i0 + row) * S_ + ck * 64 + skg * 8;
            cpasync16(base + so, g_adjf + ga);
            size_t gb = (size_t)(c0 + row) * NTOK + b * S_ + ck * 64 + skg * 8;
            cpasync16(base + 16384 + so, g_xst + gb);
        }
        cp_commit();
    };

    float acc[2][8][4] = {};
    float acc_d[2][4] = {};
    int qq = lane & 3, nn = lane >> 2;

    stage(0, 0);
    for (int kc = 0; kc < 8; kc++) {
        if (kc + 1 < 8) {
            stage(kc + 1, (kc + 1) & 1);
            cp_wait<1>();
        } else {
            cp_wait<0>();
        }
        __syncthreads();
        uint32_t AD = stage0 + (uint32_t)(kc & 1) * ATT_STAGE;
        uint32_t BS = AD + 16384;
#pragma unroll
        for (int ks = 0; ks < 4; ks++) {
            uint32_t ad[2][4];
#pragma unroll
            for (int mt = 0; mt < 2; mt++) {
                int r = wm * 32 + mt * 16 + (lane & 15);
                int kb = ks * 32 + (lane >> 4) * 16;
                ldsm4(ad[mt][0], ad[mt][1], ad[mt][2], ad[mt][3],
                      AD + swz((uint32_t)(r * 128 + kb)));
            }
            // denominator fragment: B col0 = e2, other cols 0
            {
                int jb = kc * 64 + ks * 16 + 2 * qq;
                uint32_t v0 = 0, v1 = 0;
                if (nn == 0) {
                    asm volatile("ld.shared.b32 %0, [%1];" : "=r"(v0) : "r"(E2 + jb * 2));
                    asm volatile("ld.shared.b32 %0, [%1];" : "=r"(v1) : "r"(E2 + (jb + 8) * 2));
                }
#pragma unroll
                for (int mt = 0; mt < 2; mt++)
                    mma_fp16(acc_d[mt], ad[mt], v0, v1);
            }
#pragma unroll
            for (int nq = 0; nq < 4; nq++) {
                int r = wn * 64 + nq * 16 + (lane & 7) + ((lane >> 4) & 1) * 8;
                int kb = ks * 32 + ((lane >> 3) & 1) * 16;
                uint32_t off = swz((uint32_t)(r * 128 + kb));
                uint32_t bs[4];
                ldsm4(bs[0], bs[1], bs[2], bs[3], BS + off);
#pragma unroll
                for (int mt = 0; mt < 2; mt++) {
                    mma_fp16(acc[mt][nq * 2],     ad[mt], bs[0], bs[1]);
                    mma_fp16(acc[mt][nq * 2 + 1], ad[mt], bs[2], bs[3]);
                }
            }
        }
        __syncthreads();
    }

    // epilogue: denom = col0 of acc_d (held by lane%4==0), normalize + fallback
    const float* cs = g_colsum + (b << 10);
#pragma unroll
    for (int mt = 0; mt < 2; mt++) {
        int r0 = i0 + wm * 32 + mt * 16 + (lane >> 2);
        float d0 = __shfl_sync(0xFFFFFFFFu, acc_d[mt][0], lane & 28);
        float d1 = __shfl_sync(0xFFFFFFFFu, acc_d[mt][2], lane & 28);
        float q0 = (d0 > 0.f) ? (1.0f / d0) : 0.f;
        float q1 = (d1 > 0.f) ? (1.0f / d1) : 0.f;
#pragma unroll
        for (int nt = 0; nt < 8; nt++) {
            int c = c0 + wn * 64 + nt * 8 + (lane & 3) * 2;
            float* a4 = acc[mt][nt];
            float2 o0, o1;
            if (d0 > 0.f) { o0 = make_float2(a4[0] * q0, a4[1] * q0); }
            else {
                float2 f = *(const float2*)(cs + c);
                o0 = make_float2(f.x * (1.0f / S_), f.y * (1.0f / S_));
            }
            if (d1 > 0.f) { o1 = make_float2(a4[2] * q1, a4[3] * q1); }
            else {
                float2 f = *(const float2*)(cs + c);
                o1 = make_float2(f.x * (1.0f / S_), f.y * (1.0f / S_));
            }
            *(float2*)(out + (size_t)(b * S_ + r0) * DOUT + c) = o0;
            *(float2*)(out + (size_t)(b * S_ + r0 + 8) * DOUT + c) = o1;
        }
    }
}

// ============================================================================
extern "C" void kernel_launch(void* const* d_in, const int* in_sizes, int n_in,
                              void* d_out, int out_size) {
    const float* x    = (const float*)d_in[0];
    const float* mask = (const float*)d_in[1];
    const int*   adj  = (const int*)d_in[2];
    const float* W    = (const float*)d_in[3];
    const float* attw = (const float*)d_in[4];
    float* out = (float*)d_out;

    cudaFuncSetAttribute(proj_mma, cudaFuncAttributeMaxDynamicSharedMemorySize, PROJ_SMEM);
    cudaFuncSetAttribute(att_mma, cudaFuncAttributeMaxDynamicSharedMemorySize, ATT_SMEM);

    xcvt<<<(NTOK * DIN) / (256 * 8), 256>>>(x);
    wsplit<<<dim3(DOUT / 32, DIN / 32), dim3(32, 8)>>>(W);
    adjf_kernel<<<(B_ * S_ * S_) / (256 * 8), 256>>>(adj, mask);
    proj_mma<<<dim3(DOUT / 256, NTOK / 128), 512, PROJ_SMEM>>>();
    s2exp_kernel<<<B_ * H_, 512>>>(attw, mask);
    colsum_kernel<<<(B_ * DOUT) / 256, 256>>>();
    xsplit_s<<<dim3(NTOK / 32, DOUT / 32), dim3(32, 8)>>>();
    att_mma<<<dim3(H_, S_ / 128, B_), 256, ATT_SMEM>>>(out);
}

// round 9
// speedup vs baseline: 2.1924x; 1.3762x over previous
#include <cuda_runtime.h>
#include <cuda_fp16.h>
#include <math.h>
#include <stdint.h>

#define B_   8
#define S_   512
#define DIN  1024
#define DOUT 1024
#define H_   8
#define DATT 128
#define NTOK (B_ * S_)   // 4096

// ---------------- device scratch (no allocation allowed) ----------------
__device__ __align__(16) float    g_colsum[B_ * DOUT];      // column sums (fallback)
__device__ __align__(16) uint16_t g_e2h[B_ * H_ * S_];      // masked exp(s2-max) fp16
__device__ __align__(16) uint16_t g_xf[NTOK * DIN];         // x fp16
__device__ __align__(16) uint16_t g_wt[DOUT * DIN];         // W^T fp16 [n][k]
__device__ __align__(16) uint16_t g_xst[DOUT * NTOK];       // xp^T fp16 [c][token]
__device__ __align__(16) uint16_t g_adjf[B_ * S_ * S_];     // valid adjacency fp16

// ---------------------------- helpers ----------------------------
__device__ __forceinline__ uint32_t smem_u32(const void* p) {
    uint32_t a;
    asm("{ .reg .u64 t; cvta.to.shared.u64 t, %1; cvt.u32.u64 %0, t; }" : "=r"(a) : "l"(p));
    return a;
}
__device__ __forceinline__ uint32_t swz(uint32_t off) { return off ^ ((off >> 3) & 0x70); }

__device__ __forceinline__ void cpasync16(uint32_t smem, const void* gmem) {
    asm volatile("cp.async.cg.shared.global [%0], [%1], 16;" :: "r"(smem), "l"(gmem));
}
__device__ __forceinline__ void cp_commit() {
    asm volatile("cp.async.commit_group;" ::: "memory");
}
template <int N>
__device__ __forceinline__ void cp_wait() {
    asm volatile("cp.async.wait_group %0;" :: "n"(N) : "memory");
}
__device__ __forceinline__ void ldsm4(uint32_t& r0, uint32_t& r1, uint32_t& r2, uint32_t& r3,
                                      uint32_t addr) {
    asm volatile("ldmatrix.sync.aligned.m8n8.x4.shared.b16 {%0,%1,%2,%3}, [%4];"
                 : "=r"(r0), "=r"(r1), "=r"(r2), "=r"(r3) : "r"(addr));
}
__device__ __forceinline__ void mma_fp16(float* c, const uint32_t* a, uint32_t b0, uint32_t b1) {
    asm volatile(
        "mma.sync.aligned.m16n8k16.row.col.f32.f16.f16.f32 "
        "{%0,%1,%2,%3}, {%4,%5,%6,%7}, {%8,%9}, {%0,%1,%2,%3};"
        : "+f"(c[0]), "+f"(c[1]), "+f"(c[2]), "+f"(c[3])
        : "r"(a[0]), "r"(a[1]), "r"(a[2]), "r"(a[3]), "r"(b0), "r"(b1));
}
__device__ __forceinline__ uint16_t h_bits(float f) {
    __half h = __float2half_rn(f);
    return *(uint16_t*)&h;
}
__device__ __forceinline__ uint32_t h2_bits(float x0, float x1) {
    return (uint32_t)h_bits(x0) | ((uint32_t)h_bits(x1) << 16);
}
__device__ __forceinline__ void sts16(uint32_t addr, uint16_t v) {
    asm volatile("st.shared.u16 [%0], %1;" :: "r"(addr), "h"(v));
}
__device__ __forceinline__ void sts128(uint32_t addr, uint4 v) {
    asm volatile("st.shared.v4.b32 [%0], {%1,%2,%3,%4};"
                 :: "r"(addr), "r"(v.x), "r"(v.y), "r"(v.z), "r"(v.w));
}
__device__ __forceinline__ void lds128(uint4& v, uint32_t addr) {
    asm volatile("ld.shared.v4.u32 {%0,%1,%2,%3}, [%4];"
                 : "=r"(v.x), "=r"(v.y), "=r"(v.z), "=r"(v.w) : "r"(addr));
}
__device__ __forceinline__ void lds32(uint32_t& v, uint32_t addr) {
    asm volatile("ld.shared.u32 %0, [%1];" : "=r"(v) : "r"(addr));
}
__device__ __forceinline__ uint32_t hmul2(uint32_t a, uint32_t b) {
    uint32_t d;
    asm("mul.rn.f16x2 %0, %1, %2;" : "=r"(d) : "r"(a), "r"(b));
    return d;
}

// ============================================================================
// Pre-pass 1: x -> fp16
// ============================================================================
__global__ __launch_bounds__(256) void xcvt(const float* __restrict__ src) {
    size_t base = ((size_t)blockIdx.x * 256 + threadIdx.x) * 8;
    float4 v0 = *(const float4*)(src + base);
    float4 v1 = *(const float4*)(src + base + 4);
    *(uint4*)(g_xf + base) = make_uint4(h2_bits(v0.x, v0.y), h2_bits(v0.z, v0.w),
                                        h2_bits(v1.x, v1.y), h2_bits(v1.z, v1.w));
}

// ============================================================================
// Pre-pass 2: W [k][n] -> W^T fp16 [n][k]
// ============================================================================
__global__ __launch_bounds__(256) void wsplit(const float* __restrict__ W) {
    __shared__ float tile[32][33];
    int tx = threadIdx.x, ty = threadIdx.y;
    int n0 = blockIdx.x * 32, k0 = blockIdx.y * 32;
#pragma unroll
    for (int i = 0; i < 4; i++)
        tile[ty + i * 8][tx] = W[(size_t)(k0 + ty + i * 8) * DOUT + n0 + tx];
    __syncthreads();
#pragma unroll
    for (int i = 0; i < 4; i++) {
        int n = n0 + ty + i * 8, k = k0 + tx;
        g_wt[(size_t)n * DIN + k] = h_bits(tile[tx][ty + i * 8]);
    }
}

// ============================================================================
// Pre-pass 3: adjf[b][i][j] = (adj>0 && mask_i>0) ? 1.0fp16 : 0
// ============================================================================
__global__ __launch_bounds__(256) void adjf_kernel(const int* __restrict__ adj,
                                                   const float* __restrict__ mask) {
    size_t base = ((size_t)blockIdx.x * 256 + threadIdx.x) * 8;
    int bi = (int)(base >> 9);
    uint32_t one = (mask[bi] > 0.f) ? 0x3C00u : 0u;   // fp16 1.0
    int4 a0 = *(const int4*)(adj + base);
    int4 a1 = *(const int4*)(adj + base + 4);
    uint32_t p0 = ((a0.x > 0) ? one : 0u) | (((a0.y > 0) ? one : 0u) << 16);
    uint32_t p1 = ((a0.z > 0) ? one : 0u) | (((a0.w > 0) ? one : 0u) << 16);
    uint32_t p2 = ((a1.x > 0) ? one : 0u) | (((a1.y > 0) ? one : 0u) << 16);
    uint32_t p3 = ((a1.z > 0) ? one : 0u) | (((a1.w > 0) ? one : 0u) << 16);
    *(uint4*)(g_adjf + base) = make_uint4(p0, p1, p2, p3);
}

// ============================================================================
// Kernel 4: projection GEMM, BM=128 BN=256 BK=64, 512 thr, 2-stage cp.async
//   Epilogue: in-smem transpose -> g_xst fp16 [c][token] (no fp32 output)
// ============================================================================
#define PROJ_STAGE 49152          // A 16K + B 32K
#define PROJ_SMEM (2 * PROJ_STAGE + 1024)
__global__ __launch_bounds__(512) void proj_mma() {
    extern __shared__ char dsm[];
    uint32_t sb = (smem_u32(dsm) + 1023) & ~1023u;

    int tid = threadIdx.x, lane = tid & 31, wid = tid >> 5;
    int wm = wid & 3, wn = wid >> 2;  // 4 x 4 warps, each 32m x 64n
    int m_base = blockIdx.y * 128, n_base = blockIdx.x * 256;

    int srow = tid >> 3, skg = tid & 7;

    auto stage = [&](int ck, int s) {
        uint32_t base = sb + (uint32_t)s * PROJ_STAGE;
#pragma unroll
        for (int it = 0; it < 2; it++) {  // A: 128 rows
            int row = srow + it * 64;
            uint32_t so = swz((uint32_t)(row * 128 + skg * 16));
            size_t ga = (size_t)(m_base + row) * DIN + ck * 64 + skg * 8;
            cpasync16(base + so, g_xf + ga);
        }
#pragma unroll
        for (int it = 0; it < 4; it++) {  // B: 256 rows
            int row = srow + it * 64;
            uint32_t so = swz((uint32_t)(row * 128 + skg * 16));
            size_t gb = (size_t)(n_base + row) * DIN + ck * 64 + skg * 8;
            cpasync16(base + 16384 + so, g_wt + gb);
        }
        cp_commit();
    };

    float acc[2][8][4] = {};

    stage(0, 0);
    for (int ck = 0; ck < 16; ck++) {
        if (ck + 1 < 16) {
            stage(ck + 1, (ck + 1) & 1);
            cp_wait<1>();
        } else {
            cp_wait<0>();
        }
        __syncthreads();
        uint32_t AS = sb + (uint32_t)(ck & 1) * PROJ_STAGE;
        uint32_t BS = AS + 16384;
#pragma unroll
        for (int ks = 0; ks < 4; ks++) {
            uint32_t af[2][4];
#pragma unroll
            for (int mt = 0; mt < 2; mt++) {
                int r = wm * 32 + mt * 16 + (lane & 15);
                int kb = ks * 32 + (lane >> 4) * 16;
                uint32_t off = swz((uint32_t)(r * 128 + kb));
                ldsm4(af[mt][0], af[mt][1], af[mt][2], af[mt][3], AS + off);
            }
#pragma unroll
            for (int nq = 0; nq < 4; nq++) {
                int r = wn * 64 + nq * 16 + (lane & 7) + ((lane >> 4) & 1) * 8;
                int kb = ks * 32 + ((lane >> 3) & 1) * 16;
                uint32_t off = swz((uint32_t)(r * 128 + kb));
                uint32_t bs[4];
                ldsm4(bs[0], bs[1], bs[2], bs[3], BS + off);
#pragma unroll
                for (int mt = 0; mt < 2; mt++) {
                    mma_fp16(acc[mt][nq * 2],     af[mt], bs[0], bs[1]);
                    mma_fp16(acc[mt][nq * 2 + 1], af[mt], bs[2], bs[3]);
                }
            }
        }
        __syncthreads();
    }

    // ---- epilogue: smem transpose (padded rows, conflict-free) -> g_xst ----
    const int RS = 136;  // row stride in halves: 128 + 8 pad
#pragma unroll
    for (int mt = 0; mt < 2; mt++)
#pragma unroll
        for (int nt = 0; nt < 8; nt++) {
            int r = wm * 32 + mt * 16 + (lane >> 2);
            int c = wn * 64 + nt * 8 + (lane & 3) * 2;
            float* a4 = acc[mt][nt];
            sts16(sb + (uint32_t)(c * RS + r) * 2,            h_bits(a4[0]));
            sts16(sb + (uint32_t)((c + 1) * RS + r) * 2,      h_bits(a4[1]));
            sts16(sb + (uint32_t)(c * RS + r + 8) * 2,        h_bits(a4[2]));
            sts16(sb + (uint32_t)((c + 1) * RS + r + 8) * 2,  h_bits(a4[3]));
        }
    __syncthreads();
#pragma unroll
    for (int it = 0; it < 8; it++) {
        int task = it * 512 + tid;      // 4096 tasks: 256 c x 16 token-groups
        int c = task >> 4, g = task & 15;
        uint4 v;
        lds128(v, sb + (uint32_t)(c * RS + g * 8) * 2);
        *(uint4*)(g_xst + (size_t)(n_base + c) * NTOK + m_base + g * 8) = v;
    }
}

// ============================================================================
// Kernel 5: fused s2 + max + exp + mask from fp16 xst  (block per (b,h))
// ============================================================================
__global__ __launch_bounds__(512) void s2exp_kernel(const float* __restrict__ attw,
                                                    const float* __restrict__ mask) {
    __shared__ float red[16];
    int bh = blockIdx.x;
    int b = bh >> 3, h = bh & 7;
    int tid = threadIdx.x, wid = tid >> 5, lane = tid & 31;
    const uint16_t* base = g_xst + (size_t)(h * DATT) * NTOK + b * S_ + tid;
    float acc = 0.f;
#pragma unroll 8
    for (int c = 0; c < DATT; c++) {
        __half hv = *(const __half*)(base + (size_t)c * NTOK);
        acc += __half2float(hv) * __ldg(attw + DATT + c);
    }
    float m = acc;
#pragma unroll
    for (int o = 16; o; o >>= 1) m = fmaxf(m, __shfl_xor_sync(0xFFFFFFFFu, m, o));
    if (lane == 0) red[wid] = m;
    __syncthreads();
    if (wid == 0) {
        float t = (lane < 16) ? red[lane] : -INFINITY;
#pragma unroll
        for (int o = 8; o; o >>= 1) t = fmaxf(t, __shfl_xor_sync(0xFFFFFFFFu, t, o));
        if (lane == 0) red[0] = t;
    }
    __syncthreads();
    m = red[0];
    float mj = mask[b * S_ + tid] > 0.f ? 1.f : 0.f;
    g_e2h[(size_t)bh * S_ + tid] = h_bits(mj * expf(acc - m));
}

// ============================================================================
// Kernel 6: colsum[b,c] = sum_j xst[c][b*512+j]  (one warp per (b,c))
// ============================================================================
__global__ __launch_bounds__(256) void colsum_kernel() {
    int gw = blockIdx.x * 8 + (threadIdx.x >> 5);  // 8192 (b,c) pairs
    int lane = threadIdx.x & 31;
    int b = gw >> 10, c = gw & 1023;
    const uint4* p = (const uint4*)(g_xst + (size_t)c * NTOK + b * S_);
    float s = 0.f;
#pragma unroll
    for (int it = 0; it < 2; it++) {
        uint4 v = p[it * 32 + lane];
        float2 f0 = __half22float2(*(__half2*)&v.x);
        float2 f1 = __half22float2(*(__half2*)&v.y);
        float2 f2 = __half22float2(*(__half2*)&v.z);
        float2 f3 = __half22float2(*(__half2*)&v.w);
        s += f0.x + f0.y + f1.x + f1.y + f2.x + f2.y + f3.x + f3.y;
    }
#pragma unroll
    for (int o = 16; o; o >>= 1) s += __shfl_xor_sync(0xFFFFFFFFu, s, o);
    if (lane == 0) g_colsum[(b << 10) | c] = s;
}

// ============================================================================
// Kernel 7: attention GEMM; e2 folded into A fragments (exact: adj in {0,1});
//   denominator via constant ones-column; fused normalize + fallback
// ============================================================================
#define ATT_STAGE 32768           // adj 16K + B 16K
#define ATT_SMEM (1024 + 2 * ATT_STAGE + 1024)
__global__ __launch_bounds__(256) void att_mma(float* __restrict__ out) {
    extern __shared__ char dsm[];
    uint32_t sb = (smem_u32(dsm) + 1023) & ~1023u;
    uint32_t E2 = sb;
    uint32_t stage0 = sb + 1024;

    int tid = threadIdx.x, lane = tid & 31, wid = tid >> 5;
    int wm = wid & 3, wn = wid >> 2;
    int h = blockIdx.x, i0 = blockIdx.y * 128, b = blockIdx.z;
    int c0 = h * DATT;

    // stage e2 fp16 (512 values = 1 KB)
    if (tid < 64) {
        uint4 v = ((const uint4*)(g_e2h + (size_t)(b * H_ + h) * S_))[tid];
        sts128(E2 + tid * 16, v);
    }

    int srow = tid >> 3, skg = tid & 7;

    auto stage = [&](int ck, int s) {
        uint32_t base = stage0 + (uint32_t)s * ATT_STAGE;
#pragma unroll
        for (int it = 0; it < 4; it++) {
            int row = srow + it * 32;
            uint32_t so = swz((uint32_t)(row * 128 + skg * 16));
            size_t ga = (size_t)(b * S_ + i0 + row) * S_ + ck * 64 + skg * 8;
            cpasync16(base + so, g_adjf + ga);
            size_t gb = (size_t)(c0 + row) * NTOK + b * S_ + ck * 64 + skg * 8;
            cpasync16(base + 16384 + so, g_xst + gb);
        }
        cp_commit();
    };

    float acc[2][8][4] = {};
    float acc_d[2][4] = {};
    int nn = lane >> 2;

    stage(0, 0);
    for (int kc = 0; kc < 8; kc++) {
        if (kc + 1 < 8) {
            stage(kc + 1, (kc + 1) & 1);
            cp_wait<1>();
        } else {
            cp_wait<0>();
        }
        __syncthreads();
        uint32_t AD = stage0 + (uint32_t)(kc & 1) * ATT_STAGE;
        uint32_t BS = AD + 16384;
#pragma unroll
        for (int ks = 0; ks < 4; ks++) {
            uint32_t ad[2][4];
#pragma unroll
            for (int mt = 0; mt < 2; mt++) {
                int r = wm * 32 + mt * 16 + (lane & 15);
                int kb = ks * 32 + (lane >> 4) * 16;
                ldsm4(ad[mt][0], ad[mt][1], ad[mt][2], ad[mt][3],
                      AD + swz((uint32_t)(r * 128 + kb)));
            }
            // fold e2[j] into A fragments (adj in {0,1} -> product exact fp16)
            {
                int kj = kc * 64 + ks * 16 + (lane & 3) * 2;
                uint32_t ea, eb;
                lds32(ea, E2 + kj * 2);
                lds32(eb, E2 + kj * 2 + 16);
#pragma unroll
                for (int mt = 0; mt < 2; mt++) {
                    ad[mt][0] = hmul2(ad[mt][0], ea);
                    ad[mt][1] = hmul2(ad[mt][1], ea);
                    ad[mt][2] = hmul2(ad[mt][2], eb);
                    ad[mt][3] = hmul2(ad[mt][3], eb);
                }
            }
            // denominator: B = ones column at n=0
            {
                uint32_t v = (nn == 0) ? 0x3C003C00u : 0u;
#pragma unroll
                for (int mt = 0; mt < 2; mt++)
                    mma_fp16(acc_d[mt], ad[mt], v, v);
            }
#pragma unroll
            for (int nq = 0; nq < 4; nq++) {
                int r = wn * 64 + nq * 16 + (lane & 7) + ((lane >> 4) & 1) * 8;
                int kb = ks * 32 + ((lane >> 3) & 1) * 16;
                uint32_t off = swz((uint32_t)(r * 128 + kb));
                uint32_t bs[4];
                ldsm4(bs[0], bs[1], bs[2], bs[3], BS + off);
#pragma unroll
                for (int mt = 0; mt < 2; mt++) {
                    mma_fp16(acc[mt][nq * 2],     ad[mt], bs[0], bs[1]);
                    mma_fp16(acc[mt][nq * 2 + 1], ad[mt], bs[2], bs[3]);
                }
            }
        }
        __syncthreads();
    }

    // epilogue: denom = col0 of acc_d (held by lane%4==0), normalize + fallback
    const float* cs = g_colsum + (b << 10);
#pragma unroll
    for (int mt = 0; mt < 2; mt++) {
        int r0 = i0 + wm * 32 + mt * 16 + (lane >> 2);
        float d0 = __shfl_sync(0xFFFFFFFFu, acc_d[mt][0], lane & 28);
        float d1 = __shfl_sync(0xFFFFFFFFu, acc_d[mt][2], lane & 28);
        float q0 = (d0 > 0.f) ? (1.0f / d0) : 0.f;
        float q1 = (d1 > 0.f) ? (1.0f / d1) : 0.f;
#pragma unroll
        for (int nt = 0; nt < 8; nt++) {
            int c = c0 + wn * 64 + nt * 8 + (lane & 3) * 2;
            float* a4 = acc[mt][nt];
            float2 o0, o1;
            if (d0 > 0.f) { o0 = make_float2(a4[0] * q0, a4[1] * q0); }
            else {
                float2 f = *(const float2*)(cs + c);
                o0 = make_float2(f.x * (1.0f / S_), f.y * (1.0f / S_));
            }
            if (d1 > 0.f) { o1 = make_float2(a4[2] * q1, a4[3] * q1); }
            else {
                float2 f = *(const float2*)(cs + c);
                o1 = make_float2(f.x * (1.0f / S_), f.y * (1.0f / S_));
            }
            *(float2*)(out + (size_t)(b * S_ + r0) * DOUT + c) = o0;
            *(float2*)(out + (size_t)(b * S_ + r0 + 8) * DOUT + c) = o1;
        }
    }
}

// ============================================================================
extern "C" void kernel_launch(void* const* d_in, const int* in_sizes, int n_in,
                              void* d_out, int out_size) {
    const float* x    = (const float*)d_in[0];
    const float* mask = (const float*)d_in[1];
    const int*   adj  = (const int*)d_in[2];
    const float* W    = (const float*)d_in[3];
    const float* attw = (const float*)d_in[4];
    float* out = (float*)d_out;

    cudaFuncSetAttribute(proj_mma, cudaFuncAttributeMaxDynamicSharedMemorySize, PROJ_SMEM);
    cudaFuncSetAttribute(att_mma, cudaFuncAttributeMaxDynamicSharedMemorySize, ATT_SMEM);

    xcvt<<<(NTOK * DIN) / (256 * 8), 256>>>(x);
    wsplit<<<dim3(DOUT / 32, DIN / 32), dim3(32, 8)>>>(W);
    adjf_kernel<<<(B_ * S_ * S_) / (256 * 8), 256>>>(adj, mask);
    proj_mma<<<dim3(DOUT / 256, NTOK / 128), 512, PROJ_SMEM>>>();
    s2exp_kernel<<<B_ * H_, 512>>>(attw, mask);
    colsum_kernel<<<(B_ * DOUT) / 8 / 256 * 8, 256>>>();
    att_mma<<<dim3(H_, S_ / 128, B_), 256, ATT_SMEM>>>(out);
}

// round 10
// speedup vs baseline: 2.4059x; 1.0973x over previous
#include <cuda_runtime.h>
#include <cuda_fp16.h>
#include <math.h>
#include <stdint.h>

#define B_   8
#define S_   512
#define DIN  1024
#define DOUT 1024
#define H_   8
#define DATT 128
#define NTOK (B_ * S_)   // 4096

// ---------------- device scratch (no allocation allowed) ----------------
__device__ __align__(16) float    g_colsum[B_ * DOUT];      // column sums (fallback)
__device__ __align__(16) uint16_t g_e2h[B_ * H_ * S_];      // masked exp(s2-max) fp16
__device__ __align__(16) uint16_t g_xf[NTOK * DIN];         // x fp16
__device__ __align__(16) uint16_t g_wt[DOUT * DIN];         // W^T fp16 [n][k]
__device__ __align__(16) uint16_t g_xst[DOUT * NTOK];       // xp^T fp16 [c][token]
__device__ __align__(16) uint16_t g_adjf[B_ * S_ * S_];     // valid adjacency fp16

// ---------------------------- helpers ----------------------------
__device__ __forceinline__ uint32_t smem_u32(const void* p) {
    uint32_t a;
    asm("{ .reg .u64 t; cvta.to.shared.u64 t, %1; cvt.u32.u64 %0, t; }" : "=r"(a) : "l"(p));
    return a;
}
__device__ __forceinline__ uint32_t swz(uint32_t off) { return off ^ ((off >> 3) & 0x70); }

__device__ __forceinline__ void cpasync16(uint32_t smem, const void* gmem) {
    asm volatile("cp.async.cg.shared.global [%0], [%1], 16;" :: "r"(smem), "l"(gmem));
}
__device__ __forceinline__ void cp_commit() {
    asm volatile("cp.async.commit_group;" ::: "memory");
}
template <int N>
__device__ __forceinline__ void cp_wait() {
    asm volatile("cp.async.wait_group %0;" :: "n"(N) : "memory");
}
__device__ __forceinline__ void ldsm4(uint32_t& r0, uint32_t& r1, uint32_t& r2, uint32_t& r3,
                                      uint32_t addr) {
    asm volatile("ldmatrix.sync.aligned.m8n8.x4.shared.b16 {%0,%1,%2,%3}, [%4];"
                 : "=r"(r0), "=r"(r1), "=r"(r2), "=r"(r3) : "r"(addr));
}
__device__ __forceinline__ void mma_fp16(float* c, const uint32_t* a, uint32_t b0, uint32_t b1) {
    asm volatile(
        "mma.sync.aligned.m16n8k16.row.col.f32.f16.f16.f32 "
        "{%0,%1,%2,%3}, {%4,%5,%6,%7}, {%8,%9}, {%0,%1,%2,%3};"
        : "+f"(c[0]), "+f"(c[1]), "+f"(c[2]), "+f"(c[3])
        : "r"(a[0]), "r"(a[1]), "r"(a[2]), "r"(a[3]), "r"(b0), "r"(b1));
}
__device__ __forceinline__ uint16_t h_bits(float f) {
    __half h = __float2half_rn(f);
    return *(uint16_t*)&h;
}
__device__ __forceinline__ uint32_t h2_bits(float x0, float x1) {
    return (uint32_t)h_bits(x0) | ((uint32_t)h_bits(x1) << 16);
}
__device__ __forceinline__ void sts16(uint32_t addr, uint16_t v) {
    asm volatile("st.shared.u16 [%0], %1;" :: "r"(addr), "h"(v));
}
__device__ __forceinline__ void sts128(uint32_t addr, uint4 v) {
    asm volatile("st.shared.v4.b32 [%0], {%1,%2,%3,%4};"
                 :: "r"(addr), "r"(v.x), "r"(v.y), "r"(v.z), "r"(v.w));
}
__device__ __forceinline__ void lds128(uint4& v, uint32_t addr) {
    asm volatile("ld.shared.v4.u32 {%0,%1,%2,%3}, [%4];"
                 : "=r"(v.x), "=r"(v.y), "=r"(v.z), "=r"(v.w) : "r"(addr));
}
__device__ __forceinline__ void lds32(uint32_t& v, uint32_t addr) {
    asm volatile("ld.shared.u32 %0, [%1];" : "=r"(v) : "r"(addr));
}
__device__ __forceinline__ uint32_t hmul2(uint32_t a, uint32_t b) {
    uint32_t d;
    asm("mul.rn.f16x2 %0, %1, %2;" : "=r"(d) : "r"(a), "r"(b));
    return d;
}

// ============================================================================
// Kernel 1 (merged pre-pass):
//   blocks [0,2048):      x -> fp16
//   blocks [2048,3072):   W -> W^T fp16
//   blocks [3072,4096):   adjacency -> fp16 with mask_i
//   blocks [4096,4128):   zero g_colsum
// ============================================================================
__global__ __launch_bounds__(256) void prepass(const float* __restrict__ x,
                                               const float* __restrict__ W,
                                               const int* __restrict__ adj,
                                               const float* __restrict__ mask) {
    __shared__ float tile[32][33];
    int blk = blockIdx.x, tid = threadIdx.x;
    if (blk < 2048) {
        size_t base = ((size_t)blk * 256 + tid) * 8;
        float4 v0 = *(const float4*)(x + base);
        float4 v1 = *(const float4*)(x + base + 4);
        *(uint4*)(g_xf + base) = make_uint4(h2_bits(v0.x, v0.y), h2_bits(v0.z, v0.w),
                                            h2_bits(v1.x, v1.y), h2_bits(v1.z, v1.w));
    } else if (blk < 3072) {
        int bb = blk - 2048;
        int n0 = (bb & 31) * 32, k0 = (bb >> 5) * 32;
        int tx = tid & 31, ty = tid >> 5;
#pragma unroll
        for (int i = 0; i < 4; i++)
            tile[ty + i * 8][tx] = W[(size_t)(k0 + ty + i * 8) * DOUT + n0 + tx];
        __syncthreads();
#pragma unroll
        for (int i = 0; i < 4; i++) {
            int n = n0 + ty + i * 8, k = k0 + tx;
            g_wt[(size_t)n * DIN + k] = h_bits(tile[tx][ty + i * 8]);
        }
    } else if (blk < 4096) {
        size_t base = ((size_t)(blk - 3072) * 256 + tid) * 8;
        int bi = (int)(base >> 9);
        uint32_t one = (mask[bi] > 0.f) ? 0x3C00u : 0u;   // fp16 1.0
        int4 a0 = *(const int4*)(adj + base);
        int4 a1 = *(const int4*)(adj + base + 4);
        uint32_t p0 = ((a0.x > 0) ? one : 0u) | (((a0.y > 0) ? one : 0u) << 16);
        uint32_t p1 = ((a0.z > 0) ? one : 0u) | (((a0.w > 0) ? one : 0u) << 16);
        uint32_t p2 = ((a1.x > 0) ? one : 0u) | (((a1.y > 0) ? one : 0u) << 16);
        uint32_t p3 = ((a1.z > 0) ? one : 0u) | (((a1.w > 0) ? one : 0u) << 16);
        *(uint4*)(g_adjf + base) = make_uint4(p0, p1, p2, p3);
    } else {
        g_colsum[(blk - 4096) * 256 + tid] = 0.f;
    }
}

// ============================================================================
// Kernel 2: projection GEMM, BM=128 BN=256 BK=128 (2 sub-tiles of 64),
//   512 thr, 2-stage cp.async; epilogue: smem transpose -> g_xst + colsum atomics
// ============================================================================
#define PROJ_STAGE 98304          // A 2x16K + B 2x32K
#define PROJ_SMEM (2 * PROJ_STAGE + 1024)
__global__ __launch_bounds__(512) void proj_mma() {
    extern __shared__ char dsm[];
    uint32_t sb = (smem_u32(dsm) + 1023) & ~1023u;

    int tid = threadIdx.x, lane = tid & 31, wid = tid >> 5;
    int wm = wid & 3, wn = wid >> 2;  // 4 x 4 warps, each 32m x 64n
    int m_base = blockIdx.y * 128, n_base = blockIdx.x * 256;

    int srow = tid >> 3, skg = tid & 7;

    auto stage = [&](int ck, int s) {
        uint32_t base = sb + (uint32_t)s * PROJ_STAGE;
#pragma unroll
        for (int sub = 0; sub < 2; sub++) {
#pragma unroll
            for (int it = 0; it < 2; it++) {  // A: 128 rows
                int row = srow + it * 64;
                uint32_t so = swz((uint32_t)(row * 128 + skg * 16));
                size_t ga = (size_t)(m_base + row) * DIN + ck * 128 + sub * 64 + skg * 8;
                cpasync16(base + sub * 16384 + so, g_xf + ga);
            }
#pragma unroll
            for (int it = 0; it < 4; it++) {  // B: 256 rows
                int row = srow + it * 64;
                uint32_t so = swz((uint32_t)(row * 128 + skg * 16));
                size_t gb = (size_t)(n_base + row) * DIN + ck * 128 + sub * 64 + skg * 8;
                cpasync16(base + 32768 + sub * 32768 + so, g_wt + gb);
            }
        }
        cp_commit();
    };

    float acc[2][8][4] = {};

    stage(0, 0);
    for (int ck = 0; ck < 8; ck++) {
        if (ck + 1 < 8) {
            stage(ck + 1, (ck + 1) & 1);
            cp_wait<1>();
        } else {
            cp_wait<0>();
        }
        __syncthreads();
        uint32_t cbase = sb + (uint32_t)(ck & 1) * PROJ_STAGE;
#pragma unroll
        for (int sub = 0; sub < 2; sub++) {
            uint32_t AS = cbase + sub * 16384;
            uint32_t BS = cbase + 32768 + sub * 32768;
#pragma unroll
            for (int ks = 0; ks < 4; ks++) {
                uint32_t af[2][4];
#pragma unroll
                for (int mt = 0; mt < 2; mt++) {
                    int r = wm * 32 + mt * 16 + (lane & 15);
                    int kb = ks * 32 + (lane >> 4) * 16;
                    uint32_t off = swz((uint32_t)(r * 128 + kb));
                    ldsm4(af[mt][0], af[mt][1], af[mt][2], af[mt][3], AS + off);
                }
#pragma unroll
                for (int nq = 0; nq < 4; nq++) {
                    int r = wn * 64 + nq * 16 + (lane & 7) + ((lane >> 4) & 1) * 8;
                    int kb = ks * 32 + ((lane >> 3) & 1) * 16;
                    uint32_t off = swz((uint32_t)(r * 128 + kb));
                    uint32_t bs[4];
                    ldsm4(bs[0], bs[1], bs[2], bs[3], BS + off);
#pragma unroll
                    for (int mt = 0; mt < 2; mt++) {
                        mma_fp16(acc[mt][nq * 2],     af[mt], bs[0], bs[1]);
                        mma_fp16(acc[mt][nq * 2 + 1], af[mt], bs[2], bs[3]);
                    }
                }
            }
        }
        __syncthreads();
    }

    // ---- epilogue: smem transpose (padded rows) -> g_xst + colsum atomics ----
    const int RS = 136;  // row stride in halves: 128 + 8 pad
#pragma unroll
    for (int mt = 0; mt < 2; mt++)
#pragma unroll
        for (int nt = 0; nt < 8; nt++) {
            int r = wm * 32 + mt * 16 + (lane >> 2);
            int c = wn * 64 + nt * 8 + (lane & 3) * 2;
            float* a4 = acc[mt][nt];
            sts16(sb + (uint32_t)(c * RS + r) * 2,            h_bits(a4[0]));
            sts16(sb + (uint32_t)((c + 1) * RS + r) * 2,      h_bits(a4[1]));
            sts16(sb + (uint32_t)(c * RS + r + 8) * 2,        h_bits(a4[2]));
            sts16(sb + (uint32_t)((c + 1) * RS + r + 8) * 2,  h_bits(a4[3]));
        }
    __syncthreads();
    int b = m_base >> 9;
#pragma unroll
    for (int it = 0; it < 8; it++) {
        int task = it * 512 + tid;      // 4096 tasks: 256 c x 16 token-groups
        int c = task >> 4, g = task & 15;
        uint4 v;
        lds128(v, sb + (uint32_t)(c * RS + g * 8) * 2);
        *(uint4*)(g_xst + (size_t)(n_base + c) * NTOK + m_base + g * 8) = v;
        // colsum partial: sum 8 halves, reduce over the 16 lanes sharing c
        float2 f0 = __half22float2(*(__half2*)&v.x);
        float2 f1 = __half22float2(*(__half2*)&v.y);
        float2 f2 = __half22float2(*(__half2*)&v.z);
        float2 f3 = __half22float2(*(__half2*)&v.w);
        float s = f0.x + f0.y + f1.x + f1.y + f2.x + f2.y + f3.x + f3.y;
#pragma unroll
        for (int o = 8; o; o >>= 1) s += __shfl_xor_sync(0xFFFFFFFFu, s, o);
        if ((tid & 15) == 0) atomicAdd(&g_colsum[(b << 10) + n_base + c], s);
    }
}

// ============================================================================
// Kernel 3: fused s2 + max + exp + mask from fp16 xst  (block per (b,h))
// ============================================================================
__global__ __launch_bounds__(512) void s2exp_kernel(const float* __restrict__ attw,
                                                    const float* __restrict__ mask) {
    __shared__ float red[16];
    int bh = blockIdx.x;
    int b = bh >> 3, h = bh & 7;
    int tid = threadIdx.x, wid = tid >> 5, lane = tid & 31;
    const uint16_t* base = g_xst + (size_t)(h * DATT) * NTOK + b * S_ + tid;
    float acc = 0.f;
#pragma unroll 8
    for (int c = 0; c < DATT; c++) {
        __half hv = *(const __half*)(base + (size_t)c * NTOK);
        acc += __half2float(hv) * __ldg(attw + DATT + c);
    }
    float m = acc;
#pragma unroll
    for (int o = 16; o; o >>= 1) m = fmaxf(m, __shfl_xor_sync(0xFFFFFFFFu, m, o));
    if (lane == 0) red[wid] = m;
    __syncthreads();
    if (wid == 0) {
        float t = (lane < 16) ? red[lane] : -INFINITY;
#pragma unroll
        for (int o = 8; o; o >>= 1) t = fmaxf(t, __shfl_xor_sync(0xFFFFFFFFu, t, o));
        if (lane == 0) red[0] = t;
    }
    __syncthreads();
    m = red[0];
    float mj = mask[b * S_ + tid] > 0.f ? 1.f : 0.f;
    g_e2h[(size_t)bh * S_ + tid] = h_bits(mj * expf(acc - m));
}

// ============================================================================
// Kernel 4: attention GEMM, BK=128 (2 sub-tiles); e2 folded into A fragments;
//   denominator via ones-column; fused normalize + fallback
// ============================================================================
#define ATT_STAGE 65536           // adj 2x16K + B 2x16K
#define ATT_SMEM (1024 + 2 * ATT_STAGE + 1024)
__global__ __launch_bounds__(256) void att_mma(float* __restrict__ out) {
    extern __shared__ char dsm[];
    uint32_t sb = (smem_u32(dsm) + 1023) & ~1023u;
    uint32_t E2 = sb;
    uint32_t stage0 = sb + 1024;

    int tid = threadIdx.x, lane = tid & 31, wid = tid >> 5;
    int wm = wid & 3, wn = wid >> 2;
    int h = blockIdx.x, i0 = blockIdx.y * 128, b = blockIdx.z;
    int c0 = h * DATT;

    // stage e2 fp16 (512 values = 1 KB)
    if (tid < 64) {
        uint4 v = ((const uint4*)(g_e2h + (size_t)(b * H_ + h) * S_))[tid];
        sts128(E2 + tid * 16, v);
    }

    int srow = tid >> 3, skg = tid & 7;

    auto stage = [&](int ck, int s) {
        uint32_t base = stage0 + (uint32_t)s * ATT_STAGE;
#pragma unroll
        for (int sub = 0; sub < 2; sub++) {
#pragma unroll
            for (int it = 0; it < 4; it++) {
                int row = srow + it * 32;
                uint32_t so = swz((uint32_t)(row * 128 + skg * 16));
                size_t ga = (size_t)(b * S_ + i0 + row) * S_ + ck * 128 + sub * 64 + skg * 8;
                cpasync16(base + sub * 16384 + so, g_adjf + ga);
                size_t gb = (size_t)(c0 + row) * NTOK + b * S_ + ck * 128 + sub * 64 + skg * 8;
                cpasync16(base + 32768 + sub * 16384 + so, g_xst + gb);
            }
        }
        cp_commit();
    };

    float acc[2][8][4] = {};
    float acc_d[2][4] = {};
    int nn = lane >> 2;

    stage(0, 0);
    for (int kc = 0; kc < 4; kc++) {
        if (kc + 1 < 4) {
            stage(kc + 1, (kc + 1) & 1);
            cp_wait<1>();
        } else {
            cp_wait<0>();
        }
        __syncthreads();
        uint32_t cbase = stage0 + (uint32_t)(kc & 1) * ATT_STAGE;
#pragma unroll
        for (int sub = 0; sub < 2; sub++) {
            uint32_t AD = cbase + sub * 16384;
            uint32_t BS = cbase + 32768 + sub * 16384;
#pragma unroll
            for (int ks = 0; ks < 4; ks++) {
                uint32_t ad[2][4];
#pragma unroll
                for (int mt = 0; mt < 2; mt++) {
                    int r = wm * 32 + mt * 16 + (lane & 15);
                    int kb = ks * 32 + (lane >> 4) * 16;
                    ldsm4(ad[mt][0], ad[mt][1], ad[mt][2], ad[mt][3],
                          AD + swz((uint32_t)(r * 128 + kb)));
                }
                // fold e2[j] into A fragments (adj in {0,1} -> exact fp16)
                {
                    int kj = kc * 128 + sub * 64 + ks * 16 + (lane & 3) * 2;
                    uint32_t ea, eb;
                    lds32(ea, E2 + kj * 2);
                    lds32(eb, E2 + kj * 2 + 16);
#pragma unroll
                    for (int mt = 0; mt < 2; mt++) {
                        ad[mt][0] = hmul2(ad[mt][0], ea);
                        ad[mt][1] = hmul2(ad[mt][1], ea);
                        ad[mt][2] = hmul2(ad[mt][2], eb);
                        ad[mt][3] = hmul2(ad[mt][3], eb);
                    }
                }
                // denominator: B = ones column at n=0
                {
                    uint32_t v = (nn == 0) ? 0x3C003C00u : 0u;
#pragma unroll
                    for (int mt = 0; mt < 2; mt++)
                        mma_fp16(acc_d[mt], ad[mt], v, v);
                }
#pragma unroll
                for (int nq = 0; nq < 4; nq++) {
                    int r = wn * 64 + nq * 16 + (lane & 7) + ((lane >> 4) & 1) * 8;
                    int kb = ks * 32 + ((lane >> 3) & 1) * 16;
                    uint32_t off = swz((uint32_t)(r * 128 + kb));
                    uint32_t bs[4];
                    ldsm4(bs[0], bs[1], bs[2], bs[3], BS + off);
#pragma unroll
                    for (int mt = 0; mt < 2; mt++) {
                        mma_fp16(acc[mt][nq * 2],     ad[mt], bs[0], bs[1]);
                        mma_fp16(acc[mt][nq * 2 + 1], ad[mt], bs[2], bs[3]);
                    }
                }
            }
        }
        __syncthreads();
    }

    // epilogue: denom = col0 of acc_d (held by lane%4==0), normalize + fallback
    const float* cs = g_colsum + (b << 10);
#pragma unroll
    for (int mt = 0; mt < 2; mt++) {
        int r0 = i0 + wm * 32 + mt * 16 + (lane >> 2);
        float d0 = __shfl_sync(0xFFFFFFFFu, acc_d[mt][0], lane & 28);
        float d1 = __shfl_sync(0xFFFFFFFFu, acc_d[mt][2], lane & 28);
        float q0 = (d0 > 0.f) ? (1.0f / d0) : 0.f;
        float q1 = (d1 > 0.f) ? (1.0f / d1) : 0.f;
#pragma unroll
        for (int nt = 0; nt < 8; nt++) {
            int c = c0 + wn * 64 + nt * 8 + (lane & 3) * 2;
            float* a4 = acc[mt][nt];
            float2 o0, o1;
            if (d0 > 0.f) { o0 = make_float2(a4[0] * q0, a4[1] * q0); }
            else {
                float2 f = *(const float2*)(cs + c);
                o0 = make_float2(f.x * (1.0f / S_), f.y * (1.0f / S_));
            }
            if (d1 > 0.f) { o1 = make_float2(a4[2] * q1, a4[3] * q1); }
            else {
                float2 f = *(const float2*)(cs + c);
                o1 = make_float2(f.x * (1.0f / S_), f.y * (1.0f / S_));
            }
            *(float2*)(out + (size_t)(b * S_ + r0) * DOUT + c) = o0;
            *(float2*)(out + (size_t)(b * S_ + r0 + 8) * DOUT + c) = o1;
        }
    }
}

// ============================================================================
extern "C" void kernel_launch(void* const* d_in, const int* in_sizes, int n_in,
                              void* d_out, int out_size) {
    const float* x    = (const float*)d_in[0];
    const float* mask = (const float*)d_in[1];
    const int*   adj  = (const int*)d_in[2];
    const float* W    = (const float*)d_in[3];
    const float* attw = (const float*)d_in[4];
    float* out = (float*)d_out;

    cudaFuncSetAttribute(proj_mma, cudaFuncAttributeMaxDynamicSharedMemorySize, PROJ_SMEM);
    cudaFuncSetAttribute(att_mma, cudaFuncAttributeMaxDynamicSharedMemorySize, ATT_SMEM);

    prepass<<<4128, 256>>>(x, W, adj, mask);
    proj_mma<<<dim3(DOUT / 256, NTOK / 128), 512, PROJ_SMEM>>>();
    s2exp_kernel<<<B_ * H_, 512>>>(attw, mask);
    att_mma<<<dim3(H_, S_ / 128, B_), 256, ATT_SMEM>>>(out);
}

// round 11
// speedup vs baseline: 2.6795x; 1.1137x over previous
#include <cuda_runtime.h>
#include <cuda_fp16.h>
#include <math.h>
#include <stdint.h>

#define B_   8
#define S_   512
#define DIN  1024
#define DOUT 1024
#define H_   8
#define DATT 128
#define NTOK (B_ * S_)   // 4096

// ---------------- device scratch (no allocation allowed) ----------------
__device__ __align__(16) float    g_colsum[B_ * DOUT];      // column sums (fallback)
__device__ __align__(16) float    g_s2[B_ * H_ * S_];       // raw attention logits
__device__ __align__(16) uint16_t g_e2h[B_ * H_ * S_];      // masked exp(s2-max) fp16
__device__ __align__(16) uint16_t g_xf[NTOK * DIN];         // x fp16
__device__ __align__(16) uint16_t g_wt[DOUT * DIN];         // W^T fp16 [n][k]
__device__ __align__(16) uint16_t g_xst[DOUT * NTOK];       // xp^T fp16 [c][token]
__device__ __align__(16) uint16_t g_adjf[B_ * S_ * S_];     // valid adjacency fp16

// ---------------------------- helpers ----------------------------
__device__ __forceinline__ uint32_t smem_u32(const void* p) {
    uint32_t a;
    asm("{ .reg .u64 t; cvta.to.shared.u64 t, %1; cvt.u32.u64 %0, t; }" : "=r"(a) : "l"(p));
    return a;
}
__device__ __forceinline__ uint32_t swz(uint32_t off) { return off ^ ((off >> 3) & 0x70); }

__device__ __forceinline__ void cpasync16(uint32_t smem, const void* gmem) {
    asm volatile("cp.async.cg.shared.global [%0], [%1], 16;" :: "r"(smem), "l"(gmem));
}
__device__ __forceinline__ void cp_commit() {
    asm volatile("cp.async.commit_group;" ::: "memory");
}
template <int N>
__device__ __forceinline__ void cp_wait() {
    asm volatile("cp.async.wait_group %0;" :: "n"(N) : "memory");
}
__device__ __forceinline__ void ldsm4(uint32_t& r0, uint32_t& r1, uint32_t& r2, uint32_t& r3,
                                      uint32_t addr) {
    asm volatile("ldmatrix.sync.aligned.m8n8.x4.shared.b16 {%0,%1,%2,%3}, [%4];"
                 : "=r"(r0), "=r"(r1), "=r"(r2), "=r"(r3) : "r"(addr));
}
__device__ __forceinline__ void mma_fp16(float* c, const uint32_t* a, uint32_t b0, uint32_t b1) {
    asm volatile(
        "mma.sync.aligned.m16n8k16.row.col.f32.f16.f16.f32 "
        "{%0,%1,%2,%3}, {%4,%5,%6,%7}, {%8,%9}, {%0,%1,%2,%3};"
        : "+f"(c[0]), "+f"(c[1]), "+f"(c[2]), "+f"(c[3])
        : "r"(a[0]), "r"(a[1]), "r"(a[2]), "r"(a[3]), "r"(b0), "r"(b1));
}
__device__ __forceinline__ uint16_t h_bits(float f) {
    __half h = __float2half_rn(f);
    return *(uint16_t*)&h;
}
__device__ __forceinline__ uint32_t h2_bits(float x0, float x1) {
    return (uint32_t)h_bits(x0) | ((uint32_t)h_bits(x1) << 16);
}
__device__ __forceinline__ void sts16(uint32_t addr, uint16_t v) {
    asm volatile("st.shared.u16 [%0], %1;" :: "r"(addr), "h"(v));
}
__device__ __forceinline__ void sts128(uint32_t addr, uint4 v) {
    asm volatile("st.shared.v4.b32 [%0], {%1,%2,%3,%4};"
                 :: "r"(addr), "r"(v.x), "r"(v.y), "r"(v.z), "r"(v.w));
}
__device__ __forceinline__ void lds128(uint4& v, uint32_t addr) {
    asm volatile("ld.shared.v4.u32 {%0,%1,%2,%3}, [%4];"
                 : "=r"(v.x), "=r"(v.y), "=r"(v.z), "=r"(v.w) : "r"(addr));
}
__device__ __forceinline__ void lds32(uint32_t& v, uint32_t addr) {
    asm volatile("ld.shared.u32 %0, [%1];" : "=r"(v) : "r"(addr));
}
__device__ __forceinline__ uint32_t hmul2(uint32_t a, uint32_t b) {
    uint32_t d;
    asm("mul.rn.f16x2 %0, %1, %2;" : "=r"(d) : "r"(a), "r"(b));
    return d;
}

// ============================================================================
// Kernel 1 (merged pre-pass)
// ============================================================================
__global__ __launch_bounds__(256) void prepass(const float* __restrict__ x,
                                               const float* __restrict__ W,
                                               const int* __restrict__ adj,
                                               const float* __restrict__ mask) {
    __shared__ float tile[32][33];
    int blk = blockIdx.x, tid = threadIdx.x;
    if (blk < 2048) {
        size_t base = ((size_t)blk * 256 + tid) * 8;
        float4 v0 = *(const float4*)(x + base);
        float4 v1 = *(const float4*)(x + base + 4);
        *(uint4*)(g_xf + base) = make_uint4(h2_bits(v0.x, v0.y), h2_bits(v0.z, v0.w),
                                            h2_bits(v1.x, v1.y), h2_bits(v1.z, v1.w));
    } else if (blk < 3072) {
        int bb = blk - 2048;
        int n0 = (bb & 31) * 32, k0 = (bb >> 5) * 32;
        int tx = tid & 31, ty = tid >> 5;
#pragma unroll
        for (int i = 0; i < 4; i++)
            tile[ty + i * 8][tx] = W[(size_t)(k0 + ty + i * 8) * DOUT + n0 + tx];
        __syncthreads();
#pragma unroll
        for (int i = 0; i < 4; i++) {
            int n = n0 + ty + i * 8, k = k0 + tx;
            g_wt[(size_t)n * DIN + k] = h_bits(tile[tx][ty + i * 8]);
        }
    } else if (blk < 4096) {
        size_t base = ((size_t)(blk - 3072) * 256 + tid) * 8;
        int bi = (int)(base >> 9);
        uint32_t one = (mask[bi] > 0.f) ? 0x3C00u : 0u;   // fp16 1.0
        int4 a0 = *(const int4*)(adj + base);
        int4 a1 = *(const int4*)(adj + base + 4);
        uint32_t p0 = ((a0.x > 0) ? one : 0u) | (((a0.y > 0) ? one : 0u) << 16);
        uint32_t p1 = ((a0.z > 0) ? one : 0u) | (((a0.w > 0) ? one : 0u) << 16);
        uint32_t p2 = ((a1.x > 0) ? one : 0u) | (((a1.y > 0) ? one : 0u) << 16);
        uint32_t p3 = ((a1.z > 0) ? one : 0u) | (((a1.w > 0) ? one : 0u) << 16);
        *(uint4*)(g_adjf + base) = make_uint4(p0, p1, p2, p3);
    } else {
        g_colsum[(blk - 4096) * 256 + tid] = 0.f;
    }
}

// ============================================================================
// Kernel 2: projection GEMM, BM=128 BN=256 BK=128, 512 thr, 2-stage cp.async
//   Epilogue: smem transpose -> g_xst fp16, colsum atomics, AND s2 logits
//   (the 2 heads in this n-tile close their 128-channel dot inside the CTA)
// ============================================================================
#define PROJ_STAGE 98304          // A 2x16K + B 2x32K
#define PROJ_SMEM (2 * PROJ_STAGE + 2048)
__global__ __launch_bounds__(512) void proj_mma(const float* __restrict__ attw) {
    extern __shared__ char dsm[];
    uint32_t sb = (smem_u32(dsm) + 1023) & ~1023u;

    int tid = threadIdx.x, lane = tid & 31, wid = tid >> 5;
    int wm = wid & 3, wn = wid >> 2;  // 4 x 4 warps, each 32m x 64n
    int m_base = blockIdx.y * 128, n_base = blockIdx.x * 256;

    int srow = tid >> 3, skg = tid & 7;

    auto stage = [&](int ck, int s) {
        uint32_t base = sb + (uint32_t)s * PROJ_STAGE;
#pragma unroll
        for (int sub = 0; sub < 2; sub++) {
#pragma unroll
            for (int it = 0; it < 2; it++) {  // A: 128 rows
                int row = srow + it * 64;
                uint32_t so = swz((uint32_t)(row * 128 + skg * 16));
                size_t ga = (size_t)(m_base + row) * DIN + ck * 128 + sub * 64 + skg * 8;
                cpasync16(base + sub * 16384 + so, g_xf + ga);
            }
#pragma unroll
            for (int it = 0; it < 4; it++) {  // B: 256 rows
                int row = srow + it * 64;
                uint32_t so = swz((uint32_t)(row * 128 + skg * 16));
                size_t gb = (size_t)(n_base + row) * DIN + ck * 128 + sub * 64 + skg * 8;
                cpasync16(base + 32768 + sub * 32768 + so, g_wt + gb);
            }
        }
        cp_commit();
    };

    float acc[2][8][4] = {};

    stage(0, 0);
    for (int ck = 0; ck < 8; ck++) {
        if (ck + 1 < 8) {
            stage(ck + 1, (ck + 1) & 1);
            cp_wait<1>();
        } else {
            cp_wait<0>();
        }
        __syncthreads();
        uint32_t cbase = sb + (uint32_t)(ck & 1) * PROJ_STAGE;
#pragma unroll
        for (int sub = 0; sub < 2; sub++) {
            uint32_t AS = cbase + sub * 16384;
            uint32_t BS = cbase + 32768 + sub * 32768;
#pragma unroll
            for (int ks = 0; ks < 4; ks++) {
                uint32_t af[2][4];
#pragma unroll
                for (int mt = 0; mt < 2; mt++) {
                    int r = wm * 32 + mt * 16 + (lane & 15);
                    int kb = ks * 32 + (lane >> 4) * 16;
                    uint32_t off = swz((uint32_t)(r * 128 + kb));
                    ldsm4(af[mt][0], af[mt][1], af[mt][2], af[mt][3], AS + off);
                }
#pragma unroll
                for (int nq = 0; nq < 4; nq++) {
                    int r = wn * 64 + nq * 16 + (lane & 7) + ((lane >> 4) & 1) * 8;
                    int kb = ks * 32 + ((lane >> 3) & 1) * 16;
                    uint32_t off = swz((uint32_t)(r * 128 + kb));
                    uint32_t bs[4];
                    ldsm4(bs[0], bs[1], bs[2], bs[3], BS + off);
#pragma unroll
                    for (int mt = 0; mt < 2; mt++) {
                        mma_fp16(acc[mt][nq * 2],     af[mt], bs[0], bs[1]);
                        mma_fp16(acc[mt][nq * 2 + 1], af[mt], bs[2], bs[3]);
                    }
                }
            }
        }
        __syncthreads();
    }

    // ---- epilogue ----
    const int RS = 136;              // transpose row stride (halves): 128 + 8 pad
    uint32_t S2P = sb + 69632;       // 2 heads x 128 rows of float partials

    // s2 partials from fp32 accumulators (before any smem overwrite hazards)
    float p[2][2] = {};
#pragma unroll
    for (int mt = 0; mt < 2; mt++)
#pragma unroll
        for (int nt = 0; nt < 8; nt++) {
            int c = wn * 64 + nt * 8 + (lane & 3) * 2;
            float w0 = __ldg(attw + DATT + (c & 127));
            float w1 = __ldg(attw + DATT + ((c + 1) & 127));
            p[mt][0] += acc[mt][nt][0] * w0 + acc[mt][nt][1] * w1;
            p[mt][1] += acc[mt][nt][2] * w0 + acc[mt][nt][3] * w1;
        }
#pragma unroll
    for (int mt = 0; mt < 2; mt++) {
#pragma unroll
        for (int o = 1; o < 4; o <<= 1) {
            p[mt][0] += __shfl_xor_sync(0xFFFFFFFFu, p[mt][0], o);
            p[mt][1] += __shfl_xor_sync(0xFFFFFFFFu, p[mt][1], o);
        }
    }

    if (tid < 256) *(float*)(dsm + (S2P - smem_u32(dsm)) + tid * 4) = 0.f;

    // transpose stores (fp16) into smem
#pragma unroll
    for (int mt = 0; mt < 2; mt++)
#pragma unroll
        for (int nt = 0; nt < 8; nt++) {
            int r = wm * 32 + mt * 16 + (lane >> 2);
            int c = wn * 64 + nt * 8 + (lane & 3) * 2;
            float* a4 = acc[mt][nt];
            sts16(sb + (uint32_t)(c * RS + r) * 2,            h_bits(a4[0]));
            sts16(sb + (uint32_t)((c + 1) * RS + r) * 2,      h_bits(a4[1]));
            sts16(sb + (uint32_t)(c * RS + r + 8) * 2,        h_bits(a4[2]));
            sts16(sb + (uint32_t)((c + 1) * RS + r + 8) * 2,  h_bits(a4[3]));
        }
    __syncthreads();

    // s2 cross-warp accumulation (2 wn-warps per head)
    if ((lane & 3) == 0) {
        int head = wn >> 1;
        int r0 = wm * 32 + (lane >> 2);
        float* s2p = (float*)(dsm + (S2P - smem_u32(dsm)));
#pragma unroll
        for (int mt = 0; mt < 2; mt++) {
            atomicAdd(&s2p[head * 128 + r0 + mt * 16], p[mt][0]);
            atomicAdd(&s2p[head * 128 + r0 + mt * 16 + 8], p[mt][1]);
        }
    }

    // transpose read -> g_xst + colsum partials
    int b = m_base >> 9;
#pragma unroll
    for (int it = 0; it < 8; it++) {
        int task = it * 512 + tid;      // 4096 tasks: 256 c x 16 token-groups
        int c = task >> 4, g = task & 15;
        uint4 v;
        lds128(v, sb + (uint32_t)(c * RS + g * 8) * 2);
        *(uint4*)(g_xst + (size_t)(n_base + c) * NTOK + m_base + g * 8) = v;
        float2 f0 = __half22float2(*(__half2*)&v.x);
        float2 f1 = __half22float2(*(__half2*)&v.y);
        float2 f2 = __half22float2(*(__half2*)&v.z);
        float2 f3 = __half22float2(*(__half2*)&v.w);
        float s = f0.x + f0.y + f1.x + f1.y + f2.x + f2.y + f3.x + f3.y;
#pragma unroll
        for (int o = 8; o; o >>= 1) s += __shfl_xor_sync(0xFFFFFFFFu, s, o);
        if ((tid & 15) == 0) atomicAdd(&g_colsum[(b << 10) + n_base + c], s);
    }
    __syncthreads();

    // write s2 logits
    if (tid < 256) {
        int head = tid >> 7, row = tid & 127;
        int h = (n_base >> 7) + head;
        float v = *(float*)(dsm + (S2P - smem_u32(dsm)) + tid * 4);
        g_s2[(size_t)(b * H_ + h) * S_ + (m_base & 511) + row] = v;
    }
}

// ============================================================================
// Kernel 3: tiny max + exp + mask  (block per (b,h), 512 threads)
// ============================================================================
__global__ __launch_bounds__(512) void expk(const float* __restrict__ mask) {
    __shared__ float red[16];
    int bh = blockIdx.x;
    int b = bh >> 3;
    int tid = threadIdx.x, wid = tid >> 5, lane = tid & 31;
    float v = g_s2[(size_t)bh * S_ + tid];
    float m = v;
#pragma unroll
    for (int o = 16; o; o >>= 1) m = fmaxf(m, __shfl_xor_sync(0xFFFFFFFFu, m, o));
    if (lane == 0) red[wid] = m;
    __syncthreads();
    if (wid == 0) {
        float t = (lane < 16) ? red[lane] : -INFINITY;
#pragma unroll
        for (int o = 8; o; o >>= 1) t = fmaxf(t, __shfl_xor_sync(0xFFFFFFFFu, t, o));
        if (lane == 0) red[0] = t;
    }
    __syncthreads();
    m = red[0];
    float mj = mask[b * S_ + tid] > 0.f ? 1.f : 0.f;
    g_e2h[(size_t)bh * S_ + tid] = h_bits(mj * expf(v - m));
}

// ============================================================================
// Kernel 4: attention GEMM, 512 thr, BM=256(i) BN=128(c) BK=128, grid=128
//   e2 folded into A fragments; ones-column denominator; fused normalize
// ============================================================================
#define ATT_STAGE 98304           // adj 2x32K + xst 2x16K
#define ATT_SMEM (1024 + 2 * ATT_STAGE + 1024)
__global__ __launch_bounds__(512) void att_mma(float* __restrict__ out) {
    extern __shared__ char dsm[];
    uint32_t sb = (smem_u32(dsm) + 1023) & ~1023u;
    uint32_t E2 = sb;
    uint32_t stage0 = sb + 1024;

    int tid = threadIdx.x, lane = tid & 31, wid = tid >> 5;
    int wm = wid & 7, wn = wid >> 3;   // 8 x 2 warps: 32 i x 64 c each
    int h = blockIdx.x, i0 = blockIdx.y * 256, b = blockIdx.z;
    int c0 = h * DATT;

    // stage e2 fp16 (512 values = 1 KB)
    if (tid < 64) {
        uint4 v = ((const uint4*)(g_e2h + (size_t)(b * H_ + h) * S_))[tid];
        sts128(E2 + tid * 16, v);
    }

    int srow = tid >> 3, skg = tid & 7;

    auto stage = [&](int ck, int s) {
        uint32_t base = stage0 + (uint32_t)s * ATT_STAGE;
#pragma unroll
        for (int sub = 0; sub < 2; sub++) {
#pragma unroll
            for (int it = 0; it < 4; it++) {   // adjacency: 256 rows
                int row = srow + it * 64;
                uint32_t so = swz((uint32_t)(row * 128 + skg * 16));
                size_t ga = (size_t)(b * S_ + i0 + row) * S_ + ck * 128 + sub * 64 + skg * 8;
                cpasync16(base + sub * 32768 + so, g_adjf + ga);
            }
#pragma unroll
            for (int it = 0; it < 2; it++) {   // xst: 128 rows
                int row = srow + it * 64;
                uint32_t so = swz((uint32_t)(row * 128 + skg * 16));
                size_t gb = (size_t)(c0 + row) * NTOK + b * S_ + ck * 128 + sub * 64 + skg * 8;
                cpasync16(base + 65536 + sub * 16384 + so, g_xst + gb);
            }
        }
        cp_commit();
    };

    float acc[2][8][4] = {};
    float acc_d[2][4] = {};
    int nn = lane >> 2;

    stage(0, 0);
    for (int kc = 0; kc < 4; kc++) {
        if (kc + 1 < 4) {
            stage(kc + 1, (kc + 1) & 1);
            cp_wait<1>();
        } else {
            cp_wait<0>();
        }
        __syncthreads();
        uint32_t cbase = stage0 + (uint32_t)(kc & 1) * ATT_STAGE;
#pragma unroll
        for (int sub = 0; sub < 2; sub++) {
            uint32_t AD = cbase + sub * 32768;
            uint32_t BS = cbase + 65536 + sub * 16384;
#pragma unroll
            for (int ks = 0; ks < 4; ks++) {
                uint32_t ad[2][4];
#pragma unroll
                for (int mt = 0; mt < 2; mt++) {
                    int r = wm * 32 + mt * 16 + (lane & 15);
                    int kb = ks * 32 + (lane >> 4) * 16;
                    ldsm4(ad[mt][0], ad[mt][1], ad[mt][2], ad[mt][3],
                          AD + swz((uint32_t)(r * 128 + kb)));
                }
                // fold e2[j] into A fragments (adj in {0,1} -> exact fp16)
                {
                    int kj = kc * 128 + sub * 64 + ks * 16 + (lane & 3) * 2;
                    uint32_t ea, eb;
                    lds32(ea, E2 + kj * 2);
                    lds32(eb, E2 + kj * 2 + 16);
#pragma unroll
                    for (int mt = 0; mt < 2; mt++) {
                        ad[mt][0] = hmul2(ad[mt][0], ea);
                        ad[mt][1] = hmul2(ad[mt][1], ea);
                        ad[mt][2] = hmul2(ad[mt][2], eb);
                        ad[mt][3] = hmul2(ad[mt][3], eb);
                    }
                }
                // denominator: B = ones column at n=0
                {
                    uint32_t v = (nn == 0) ? 0x3C003C00u : 0u;
#pragma unroll
                    for (int mt = 0; mt < 2; mt++)
                        mma_fp16(acc_d[mt], ad[mt], v, v);
                }
#pragma unroll
                for (int nq = 0; nq < 4; nq++) {
                    int r = wn * 64 + nq * 16 + (lane & 7) + ((lane >> 4) & 1) * 8;
                    int kb = ks * 32 + ((lane >> 3) & 1) * 16;
                    uint32_t off = swz((uint32_t)(r * 128 + kb));
                    uint32_t bs[4];
                    ldsm4(bs[0], bs[1], bs[2], bs[3], BS + off);
#pragma unroll
                    for (int mt = 0; mt < 2; mt++) {
                        mma_fp16(acc[mt][nq * 2],     ad[mt], bs[0], bs[1]);
                        mma_fp16(acc[mt][nq * 2 + 1], ad[mt], bs[2], bs[3]);
                    }
                }
            }
        }
        __syncthreads();
    }

    // epilogue: denom = col0 of acc_d (held by lane%4==0), normalize + fallback
    const float* cs = g_colsum + (b << 10);
#pragma unroll
    for (int mt = 0; mt < 2; mt++) {
        int r0 = i0 + wm * 32 + mt * 16 + (lane >> 2);
        float d0 = __shfl_sync(0xFFFFFFFFu, acc_d[mt][0], lane & 28);
        float d1 = __shfl_sync(0xFFFFFFFFu, acc_d[mt][2], lane & 28);
        float q0 = (d0 > 0.f) ? (1.0f / d0) : 0.f;
        float q1 = (d1 > 0.f) ? (1.0f / d1) : 0.f;
#pragma unroll
        for (int nt = 0; nt < 8; nt++) {
            int c = c0 + wn * 64 + nt * 8 + (lane & 3) * 2;
            float* a4 = acc[mt][nt];
            float2 o0, o1;
            if (d0 > 0.f) { o0 = make_float2(a4[0] * q0, a4[1] * q0); }
            else {
                float2 f = *(const float2*)(cs + c);
                o0 = make_float2(f.x * (1.0f / S_), f.y * (1.0f / S_));
            }
            if (d1 > 0.f) { o1 = make_float2(a4[2] * q1, a4[3] * q1); }
            else {
                float2 f = *(const float2*)(cs + c);
                o1 = make_float2(f.x * (1.0f / S_), f.y * (1.0f / S_));
            }
            *(float2*)(out + (size_t)(b * S_ + r0) * DOUT + c) = o0;
            *(float2*)(out + (size_t)(b * S_ + r0 + 8) * DOUT + c) = o1;
        }
    }
}

// ============================================================================
extern "C" void kernel_launch(void* const* d_in, const int* in_sizes, int n_in,
                              void* d_out, int out_size) {
    const float* x    = (const float*)d_in[0];
    const float* mask = (const float*)d_in[1];
    const int*   adj  = (const int*)d_in[2];
    const float* W    = (const float*)d_in[3];
    const float* attw = (const float*)d_in[4];
    float* out = (float*)d_out;

    cudaFuncSetAttribute(proj_mma, cudaFuncAttributeMaxDynamicSharedMemorySize, PROJ_SMEM);
    cudaFuncSetAttribute(att_mma, cudaFuncAttributeMaxDynamicSharedMemorySize, ATT_SMEM);

    prepass<<<4128, 256>>>(x, W, adj, mask);
    proj_mma<<<dim3(DOUT / 256, NTOK / 128), 512, PROJ_SMEM>>>(attw);
    expk<<<B_ * H_, 512>>>(mask);
    att_mma<<<dim3(H_, S_ / 256, B_), 512, ATT_SMEM>>>(out);
}

// round 12
// speedup vs baseline: 2.6955x; 1.0060x over previous
#include <cuda_runtime.h>
#include <cuda_fp16.h>
#include <math.h>
#include <stdint.h>

#define B_   8
#define S_   512
#define DIN  1024
#define DOUT 1024
#define H_   8
#define DATT 128
#define NTOK (B_ * S_)   // 4096

// ---------------- device scratch (no allocation allowed) ----------------
__device__ __align__(16) float    g_colsum[B_ * DOUT];      // column sums (fallback)
__device__ __align__(16) float    g_s2[B_ * H_ * S_];       // raw attention logits
__device__ __align__(16) uint16_t g_e2h[B_ * H_ * S_];      // masked exp(s2-max) fp16
__device__ __align__(16) uint16_t g_xf[NTOK * DIN];         // x fp16
__device__ __align__(16) uint16_t g_wt[DOUT * DIN];         // W^T fp16 [n][k]
__device__ __align__(16) uint16_t g_xst[DOUT * NTOK];       // xp^T fp16 [c][token]
__device__ __align__(16) uint16_t g_adjf[B_ * S_ * S_];     // valid adjacency fp16

// ---------------------------- helpers ----------------------------
__device__ __forceinline__ uint32_t smem_u32(const void* p) {
    uint32_t a;
    asm("{ .reg .u64 t; cvta.to.shared.u64 t, %1; cvt.u32.u64 %0, t; }" : "=r"(a) : "l"(p));
    return a;
}
__device__ __forceinline__ uint32_t swz(uint32_t off) { return off ^ ((off >> 3) & 0x70); }

__device__ __forceinline__ void cpasync16(uint32_t smem, const void* gmem) {
    asm volatile("cp.async.cg.shared.global [%0], [%1], 16;" :: "r"(smem), "l"(gmem));
}
__device__ __forceinline__ void cp_commit() {
    asm volatile("cp.async.commit_group;" ::: "memory");
}
template <int N>
__device__ __forceinline__ void cp_wait() {
    asm volatile("cp.async.wait_group %0;" :: "n"(N) : "memory");
}
__device__ __forceinline__ void ldsm4(uint32_t& r0, uint32_t& r1, uint32_t& r2, uint32_t& r3,
                                      uint32_t addr) {
    asm volatile("ldmatrix.sync.aligned.m8n8.x4.shared.b16 {%0,%1,%2,%3}, [%4];"
                 : "=r"(r0), "=r"(r1), "=r"(r2), "=r"(r3) : "r"(addr));
}
__device__ __forceinline__ void mma_fp16(float* c, const uint32_t* a, uint32_t b0, uint32_t b1) {
    asm volatile(
        "mma.sync.aligned.m16n8k16.row.col.f32.f16.f16.f32 "
        "{%0,%1,%2,%3}, {%4,%5,%6,%7}, {%8,%9}, {%0,%1,%2,%3};"
        : "+f"(c[0]), "+f"(c[1]), "+f"(c[2]), "+f"(c[3])
        : "r"(a[0]), "r"(a[1]), "r"(a[2]), "r"(a[3]), "r"(b0), "r"(b1));
}
__device__ __forceinline__ uint16_t h_bits(float f) {
    __half h = __float2half_rn(f);
    return *(uint16_t*)&h;
}
__device__ __forceinline__ uint32_t h2_bits(float x0, float x1) {
    return (uint32_t)h_bits(x0) | ((uint32_t)h_bits(x1) << 16);
}
__device__ __forceinline__ void sts16(uint32_t addr, uint16_t v) {
    asm volatile("st.shared.u16 [%0], %1;" :: "r"(addr), "h"(v));
}
__device__ __forceinline__ void sts128(uint32_t addr, uint4 v) {
    asm volatile("st.shared.v4.b32 [%0], {%1,%2,%3,%4};"
                 :: "r"(addr), "r"(v.x), "r"(v.y), "r"(v.z), "r"(v.w));
}
__device__ __forceinline__ void lds128(uint4& v, uint32_t addr) {
    asm volatile("ld.shared.v4.u32 {%0,%1,%2,%3}, [%4];"
                 : "=r"(v.x), "=r"(v.y), "=r"(v.z), "=r"(v.w) : "r"(addr));
}
__device__ __forceinline__ void lds32(uint32_t& v, uint32_t addr) {
    asm volatile("ld.shared.u32 %0, [%1];" : "=r"(v) : "r"(addr));
}
__device__ __forceinline__ uint32_t hmul2(uint32_t a, uint32_t b) {
    uint32_t d;
    asm("mul.rn.f16x2 %0, %1, %2;" : "=r"(d) : "r"(a), "r"(b));
    return d;
}

// ============================================================================
// Kernel 1 (merged pre-pass)
// ============================================================================
__global__ __launch_bounds__(256) void prepass(const float* __restrict__ x,
                                               const float* __restrict__ W,
                                               const int* __restrict__ adj,
                                               const float* __restrict__ mask) {
    __shared__ float tile[32][33];
    int blk = blockIdx.x, tid = threadIdx.x;
    if (blk < 2048) {
        size_t base = ((size_t)blk * 256 + tid) * 8;
        float4 v0 = *(const float4*)(x + base);
        float4 v1 = *(const float4*)(x + base + 4);
        *(uint4*)(g_xf + base) = make_uint4(h2_bits(v0.x, v0.y), h2_bits(v0.z, v0.w),
                                            h2_bits(v1.x, v1.y), h2_bits(v1.z, v1.w));
    } else if (blk < 3072) {
        int bb = blk - 2048;
        int n0 = (bb & 31) * 32, k0 = (bb >> 5) * 32;
        int tx = tid & 31, ty = tid >> 5;
#pragma unroll
        for (int i = 0; i < 4; i++)
            tile[ty + i * 8][tx] = W[(size_t)(k0 + ty + i * 8) * DOUT + n0 + tx];
        __syncthreads();
#pragma unroll
        for (int i = 0; i < 4; i++) {
            int n = n0 + ty + i * 8, k = k0 + tx;
            g_wt[(size_t)n * DIN + k] = h_bits(tile[tx][ty + i * 8]);
        }
    } else if (blk < 4096) {
        size_t base = ((size_t)(blk - 3072) * 256 + tid) * 8;
        int bi = (int)(base >> 9);
        uint32_t one = (mask[bi] > 0.f) ? 0x3C00u : 0u;   // fp16 1.0
        int4 a0 = *(const int4*)(adj + base);
        int4 a1 = *(const int4*)(adj + base + 4);
        uint32_t p0 = ((a0.x > 0) ? one : 0u) | (((a0.y > 0) ? one : 0u) << 16);
        uint32_t p1 = ((a0.z > 0) ? one : 0u) | (((a0.w > 0) ? one : 0u) << 16);
        uint32_t p2 = ((a1.x > 0) ? one : 0u) | (((a1.y > 0) ? one : 0u) << 16);
        uint32_t p3 = ((a1.z > 0) ? one : 0u) | (((a1.w > 0) ? one : 0u) << 16);
        *(uint4*)(g_adjf + base) = make_uint4(p0, p1, p2, p3);
    } else {
        g_colsum[(blk - 4096) * 256 + tid] = 0.f;
    }
}

// ============================================================================
// Kernel 2: projection GEMM, BM=128 BN=256 BK=128, 512 thr, 2-stage cp.async
//   Epilogue: smem transpose -> g_xst fp16, colsum atomics, AND s2 logits
//   (the 2 heads in this n-tile close their 128-channel dot inside the CTA)
// ============================================================================
#define PROJ_STAGE 98304          // A 2x16K + B 2x32K
#define PROJ_SMEM (2 * PROJ_STAGE + 2048)
__global__ __launch_bounds__(512) void proj_mma(const float* __restrict__ attw) {
    extern __shared__ char dsm[];
    uint32_t sb = (smem_u32(dsm) + 1023) & ~1023u;

    int tid = threadIdx.x, lane = tid & 31, wid = tid >> 5;
    int wm = wid & 3, wn = wid >> 2;  // 4 x 4 warps, each 32m x 64n
    int m_base = blockIdx.y * 128, n_base = blockIdx.x * 256;

    int srow = tid >> 3, skg = tid & 7;

    auto stage = [&](int ck, int s) {
        uint32_t base = sb + (uint32_t)s * PROJ_STAGE;
#pragma unroll
        for (int sub = 0; sub < 2; sub++) {
#pragma unroll
            for (int it = 0; it < 2; it++) {  // A: 128 rows
                int row = srow + it * 64;
                uint32_t so = swz((uint32_t)(row * 128 + skg * 16));
                size_t ga = (size_t)(m_base + row) * DIN + ck * 128 + sub * 64 + skg * 8;
                cpasync16(base + sub * 16384 + so, g_xf + ga);
            }
#pragma unroll
            for (int it = 0; it < 4; it++) {  // B: 256 rows
                int row = srow + it * 64;
                uint32_t so = swz((uint32_t)(row * 128 + skg * 16));
                size_t gb = (size_t)(n_base + row) * DIN + ck * 128 + sub * 64 + skg * 8;
                cpasync16(base + 32768 + sub * 32768 + so, g_wt + gb);
            }
        }
        cp_commit();
    };

    float acc[2][8][4] = {};

    stage(0, 0);
    for (int ck = 0; ck < 8; ck++) {
        if (ck + 1 < 8) {
            stage(ck + 1, (ck + 1) & 1);
            cp_wait<1>();
        } else {
            cp_wait<0>();
        }
        __syncthreads();
        uint32_t cbase = sb + (uint32_t)(ck & 1) * PROJ_STAGE;
#pragma unroll
        for (int sub = 0; sub < 2; sub++) {
            uint32_t AS = cbase + sub * 16384;
            uint32_t BS = cbase + 32768 + sub * 32768;
#pragma unroll
            for (int ks = 0; ks < 4; ks++) {
                uint32_t af[2][4];
#pragma unroll
                for (int mt = 0; mt < 2; mt++) {
                    int r = wm * 32 + mt * 16 + (lane & 15);
                    int kb = ks * 32 + (lane >> 4) * 16;
                    uint32_t off = swz((uint32_t)(r * 128 + kb));
                    ldsm4(af[mt][0], af[mt][1], af[mt][2], af[mt][3], AS + off);
                }
#pragma unroll
                for (int nq = 0; nq < 4; nq++) {
                    int r = wn * 64 + nq * 16 + (lane & 7) + ((lane >> 4) & 1) * 8;
                    int kb = ks * 32 + ((lane >> 3) & 1) * 16;
                    uint32_t off = swz((uint32_t)(r * 128 + kb));
                    uint32_t bs[4];
                    ldsm4(bs[0], bs[1], bs[2], bs[3], BS + off);
#pragma unroll
                    for (int mt = 0; mt < 2; mt++) {
                        mma_fp16(acc[mt][nq * 2],     af[mt], bs[0], bs[1]);
                        mma_fp16(acc[mt][nq * 2 + 1], af[mt], bs[2], bs[3]);
                    }
                }
            }
        }
        __syncthreads();
    }

    // ---- epilogue ----
    const int RS = 136;              // transpose row stride (halves): 128 + 8 pad
    uint32_t S2P = sb + 69632;       // 2 heads x 128 rows of float partials

    // s2 partials from fp32 accumulators (before any smem overwrite hazards)
    float p[2][2] = {};
#pragma unroll
    for (int mt = 0; mt < 2; mt++)
#pragma unroll
        for (int nt = 0; nt < 8; nt++) {
            int c = wn * 64 + nt * 8 + (lane & 3) * 2;
            float w0 = __ldg(attw + DATT + (c & 127));
            float w1 = __ldg(attw + DATT + ((c + 1) & 127));
            p[mt][0] += acc[mt][nt][0] * w0 + acc[mt][nt][1] * w1;
            p[mt][1] += acc[mt][nt][2] * w0 + acc[mt][nt][3] * w1;
        }
#pragma unroll
    for (int mt = 0; mt < 2; mt++) {
#pragma unroll
        for (int o = 1; o < 4; o <<= 1) {
            p[mt][0] += __shfl_xor_sync(0xFFFFFFFFu, p[mt][0], o);
            p[mt][1] += __shfl_xor_sync(0xFFFFFFFFu, p[mt][1], o);
        }
    }

    if (tid < 256) *(float*)(dsm + (S2P - smem_u32(dsm)) + tid * 4) = 0.f;

    // transpose stores (fp16) into smem
#pragma unroll
    for (int mt = 0; mt < 2; mt++)
#pragma unroll
        for (int nt = 0; nt < 8; nt++) {
            int r = wm * 32 + mt * 16 + (lane >> 2);
            int c = wn * 64 + nt * 8 + (lane & 3) * 2;
            float* a4 = acc[mt][nt];
            sts16(sb + (uint32_t)(c * RS + r) * 2,            h_bits(a4[0]));
            sts16(sb + (uint32_t)((c + 1) * RS + r) * 2,      h_bits(a4[1]));
            sts16(sb + (uint32_t)(c * RS + r + 8) * 2,        h_bits(a4[2]));
            sts16(sb + (uint32_t)((c + 1) * RS + r + 8) * 2,  h_bits(a4[3]));
        }
    __syncthreads();

    // s2 cross-warp accumulation (2 wn-warps per head)
    if ((lane & 3) == 0) {
        int head = wn >> 1;
        int r0 = wm * 32 + (lane >> 2);
        float* s2p = (float*)(dsm + (S2P - smem_u32(dsm)));
#pragma unroll
        for (int mt = 0; mt < 2; mt++) {
            atomicAdd(&s2p[head * 128 + r0 + mt * 16], p[mt][0]);
            atomicAdd(&s2p[head * 128 + r0 + mt * 16 + 8], p[mt][1]);
        }
    }

    // transpose read -> g_xst + colsum partials
    int b = m_base >> 9;
#pragma unroll
    for (int it = 0; it < 8; it++) {
        int task = it * 512 + tid;      // 4096 tasks: 256 c x 16 token-groups
        int c = task >> 4, g = task & 15;
        uint4 v;
        lds128(v, sb + (uint32_t)(c * RS + g * 8) * 2);
        *(uint4*)(g_xst + (size_t)(n_base + c) * NTOK + m_base + g * 8) = v;
        float2 f0 = __half22float2(*(__half2*)&v.x);
        float2 f1 = __half22float2(*(__half2*)&v.y);
        float2 f2 = __half22float2(*(__half2*)&v.z);
        float2 f3 = __half22float2(*(__half2*)&v.w);
        float s = f0.x + f0.y + f1.x + f1.y + f2.x + f2.y + f3.x + f3.y;
#pragma unroll
        for (int o = 8; o; o >>= 1) s += __shfl_xor_sync(0xFFFFFFFFu, s, o);
        if ((tid & 15) == 0) atomicAdd(&g_colsum[(b << 10) + n_base + c], s);
    }
    __syncthreads();

    // write s2 logits
    if (tid < 256) {
        int head = tid >> 7, row = tid & 127;
        int h = (n_base >> 7) + head;
        float v = *(float*)(dsm + (S2P - smem_u32(dsm)) + tid * 4);
        g_s2[(size_t)(b * H_ + h) * S_ + (m_base & 511) + row] = v;
    }
}

// ============================================================================
// Kernel 3: tiny max + exp + mask  (block per (b,h), 512 threads)
// ============================================================================
__global__ __launch_bounds__(512) void expk(const float* __restrict__ mask) {
    __shared__ float red[16];
    int bh = blockIdx.x;
    int b = bh >> 3;
    int tid = threadIdx.x, wid = tid >> 5, lane = tid & 31;
    float v = g_s2[(size_t)bh * S_ + tid];
    float m = v;
#pragma unroll
    for (int o = 16; o; o >>= 1) m = fmaxf(m, __shfl_xor_sync(0xFFFFFFFFu, m, o));
    if (lane == 0) red[wid] = m;
    __syncthreads();
    if (wid == 0) {
        float t = (lane < 16) ? red[lane] : -INFINITY;
#pragma unroll
        for (int o = 8; o; o >>= 1) t = fmaxf(t, __shfl_xor_sync(0xFFFFFFFFu, t, o));
        if (lane == 0) red[0] = t;
    }
    __syncthreads();
    m = red[0];
    float mj = mask[b * S_ + tid] > 0.f ? 1.f : 0.f;
    g_e2h[(size_t)bh * S_ + tid] = h_bits(mj * expf(v - m));
}

// ============================================================================
// Kernel 4: attention GEMM, 512 thr, BM=256(i) BN=128(c) BK=128, grid=128
//   e2 folded into A fragments; ones-column denominator; fused normalize
// ============================================================================
#define ATT_STAGE 98304           // adj 2x32K + xst 2x16K
#define ATT_SMEM (1024 + 2 * ATT_STAGE + 1024)
__global__ __launch_bounds__(512) void att_mma(float* __restrict__ out) {
    extern __shared__ char dsm[];
    uint32_t sb = (smem_u32(dsm) + 1023) & ~1023u;
    uint32_t E2 = sb;
    uint32_t stage0 = sb + 1024;

    int tid = threadIdx.x, lane = tid & 31, wid = tid >> 5;
    int wm = wid & 7, wn = wid >> 3;   // 8 x 2 warps: 32 i x 64 c each
    int h = blockIdx.x, i0 = blockIdx.y * 256, b = blockIdx.z;
    int c0 = h * DATT;

    // stage e2 fp16 (512 values = 1 KB)
    if (tid < 64) {
        uint4 v = ((const uint4*)(g_e2h + (size_t)(b * H_ + h) * S_))[tid];
        sts128(E2 + tid * 16, v);
    }

    int srow = tid >> 3, skg = tid & 7;

    auto stage = [&](int ck, int s) {
        uint32_t base = stage0 + (uint32_t)s * ATT_STAGE;
#pragma unroll
        for (int sub = 0; sub < 2; sub++) {
#pragma unroll
            for (int it = 0; it < 4; it++) {   // adjacency: 256 rows
                int row = srow + it * 64;
                uint32_t so = swz((uint32_t)(row * 128 + skg * 16));
                size_t ga = (size_t)(b * S_ + i0 + row) * S_ + ck * 128 + sub * 64 + skg * 8;
                cpasync16(base + sub * 32768 + so, g_adjf + ga);
            }
#pragma unroll
            for (int it = 0; it < 2; it++) {   // xst: 128 rows
                int row = srow + it * 64;
                uint32_t so = swz((uint32_t)(row * 128 + skg * 16));
                size_t gb = (size_t)(c0 + row) * NTOK + b * S_ + ck * 128 + sub * 64 + skg * 8;
                cpasync16(base + 65536 + sub * 16384 + so, g_xst + gb);
            }
        }
        cp_commit();
    };

    float acc[2][8][4] = {};
    float acc_d[2][4] = {};
    int nn = lane >> 2;

    stage(0, 0);
    for (int kc = 0; kc < 4; kc++) {
        if (kc + 1 < 4) {
            stage(kc + 1, (kc + 1) & 1);
            cp_wait<1>();
        } else {
            cp_wait<0>();
        }
        __syncthreads();
        uint32_t cbase = stage0 + (uint32_t)(kc & 1) * ATT_STAGE;
#pragma unroll
        for (int sub = 0; sub < 2; sub++) {
            uint32_t AD = cbase + sub * 32768;
            uint32_t BS = cbase + 65536 + sub * 16384;
#pragma unroll
            for (int ks = 0; ks < 4; ks++) {
                uint32_t ad[2][4];
#pragma unroll
                for (int mt = 0; mt < 2; mt++) {
                    int r = wm * 32 + mt * 16 + (lane & 15);
                    int kb = ks * 32 + (lane >> 4) * 16;
                    ldsm4(ad[mt][0], ad[mt][1], ad[mt][2], ad[mt][3],
                          AD + swz((uint32_t)(r * 128 + kb)));
                }
                // fold e2[j] into A fragments (adj in {0,1} -> exact fp16)
                {
                    int kj = kc * 128 + sub * 64 + ks * 16 + (lane & 3) * 2;
                    uint32_t ea, eb;
                    lds32(ea, E2 + kj * 2);
                    lds32(eb, E2 + kj * 2 + 16);
#pragma unroll
                    for (int mt = 0; mt < 2; mt++) {
                        ad[mt][0] = hmul2(ad[mt][0], ea);
                        ad[mt][1] = hmul2(ad[mt][1], ea);
                        ad[mt][2] = hmul2(ad[mt][2], eb);
                        ad[mt][3] = hmul2(ad[mt][3], eb);
                    }
                }
                // denominator: B = ones column at n=0
                {
                    uint32_t v = (nn == 0) ? 0x3C003C00u : 0u;
#pragma unroll
                    for (int mt = 0; mt < 2; mt++)
                        mma_fp16(acc_d[mt], ad[mt], v, v);
                }
#pragma unroll
                for (int nq = 0; nq < 4; nq++) {
                    int r = wn * 64 + nq * 16 + (lane & 7) + ((lane >> 4) & 1) * 8;
                    int kb = ks * 32 + ((lane >> 3) & 1) * 16;
                    uint32_t off = swz((uint32_t)(r * 128 + kb));
                    uint32_t bs[4];
                    ldsm4(bs[0], bs[1], bs[2], bs[3], BS + off);
#pragma unroll
                    for (int mt = 0; mt < 2; mt++) {
                        mma_fp16(acc[mt][nq * 2],     ad[mt], bs[0], bs[1]);
                        mma_fp16(acc[mt][nq * 2 + 1], ad[mt], bs[2], bs[3]);
                    }
                }
            }
        }
        __syncthreads();
    }

    // epilogue: denom = col0 of acc_d (held by lane%4==0), normalize + fallback
    const float* cs = g_colsum + (b << 10);
#pragma unroll
    for (int mt = 0; mt < 2; mt++) {
        int r0 = i0 + wm * 32 + mt * 16 + (lane >> 2);
        float d0 = __shfl_sync(0xFFFFFFFFu, acc_d[mt][0], lane & 28);
        float d1 = __shfl_sync(0xFFFFFFFFu, acc_d[mt][2], lane & 28);
        float q0 = (d0 > 0.f) ? (1.0f / d0) : 0.f;
        float q1 = (d1 > 0.f) ? (1.0f / d1) : 0.f;
#pragma unroll
        for (int nt = 0; nt < 8; nt++) {
            int c = c0 + wn * 64 + nt * 8 + (lane & 3) * 2;
            float* a4 = acc[mt][nt];
            float2 o0, o1;
            if (d0 > 0.f) { o0 = make_float2(a4[0] * q0, a4[1] * q0); }
            else {
                float2 f = *(const float2*)(cs + c);
                o0 = make_float2(f.x * (1.0f / S_), f.y * (1.0f / S_));
            }
            if (d1 > 0.f) { o1 = make_float2(a4[2] * q1, a4[3] * q1); }
            else {
                float2 f = *(const float2*)(cs + c);
                o1 = make_float2(f.x * (1.0f / S_), f.y * (1.0f / S_));
            }
            *(float2*)(out + (size_t)(b * S_ + r0) * DOUT + c) = o0;
            *(float2*)(out + (size_t)(b * S_ + r0 + 8) * DOUT + c) = o1;
        }
    }
}

// ============================================================================
extern "C" void kernel_launch(void* const* d_in, const int* in_sizes, int n_in,
                              void* d_out, int out_size) {
    const float* x    = (const float*)d_in[0];
    const float* mask = (const float*)d_in[1];
    const int*   adj  = (const int*)d_in[2];
    const float* W    = (const float*)d_in[3];
    const float* attw = (const float*)d_in[4];
    float* out = (float*)d_out;

    cudaFuncSetAttribute(proj_mma, cudaFuncAttributeMaxDynamicSharedMemorySize, PROJ_SMEM);
    cudaFuncSetAttribute(att_mma, cudaFuncAttributeMaxDynamicSharedMemorySize, ATT_SMEM);

    prepass<<<4128, 256>>>(x, W, adj, mask);
    proj_mma<<<dim3(DOUT / 256, NTOK / 128), 512, PROJ_SMEM>>>(attw);
    expk<<<B_ * H_, 512>>>(mask);
    att_mma<<<dim3(H_, S_ / 256, B_), 512, ATT_SMEM>>>(out);
}

// round 13
// speedup vs baseline: 2.7149x; 1.0072x over previous
#include <cuda_runtime.h>
#include <cuda_fp16.h>
#include <math.h>
#include <stdint.h>

#define B_   8
#define S_   512
#define DIN  1024
#define DOUT 1024
#define H_   8
#define DATT 128
#define NTOK (B_ * S_)   // 4096

// ---------------- device scratch (no allocation allowed) ----------------
__device__ __align__(16) float    g_colsum[B_ * DOUT];      // column sums (fallback)
__device__ __align__(16) float    g_s2[B_ * H_ * S_];       // raw attention logits
__device__ __align__(16) uint16_t g_e2h[B_ * H_ * S_];      // masked exp(s2-max) fp16
__device__ __align__(16) uint16_t g_xf[NTOK * DIN];         // x fp16
__device__ __align__(16) uint16_t g_wt[DOUT * DIN];         // W^T fp16 [n][k]
__device__ __align__(16) uint16_t g_xst[DOUT * NTOK];       // xp^T fp16 [c][token]
__device__ __align__(16) uint16_t g_adjf[B_ * S_ * S_];     // valid adjacency fp16

// ---------------------------- helpers ----------------------------
__device__ __forceinline__ uint32_t smem_u32(const void* p) {
    uint32_t a;
    asm("{ .reg .u64 t; cvta.to.shared.u64 t, %1; cvt.u32.u64 %0, t; }" : "=r"(a) : "l"(p));
    return a;
}
__device__ __forceinline__ uint32_t swz(uint32_t off) { return off ^ ((off >> 3) & 0x70); }

__device__ __forceinline__ void cpasync16(uint32_t smem, const void* gmem) {
    asm volatile("cp.async.cg.shared.global [%0], [%1], 16;" :: "r"(smem), "l"(gmem));
}
__device__ __forceinline__ void cp_commit() {
    asm volatile("cp.async.commit_group;" ::: "memory");
}
template <int N>
__device__ __forceinline__ void cp_wait() {
    asm volatile("cp.async.wait_group %0;" :: "n"(N) : "memory");
}
__device__ __forceinline__ void ldsm4(uint32_t& r0, uint32_t& r1, uint32_t& r2, uint32_t& r3,
                                      uint32_t addr) {
    asm volatile("ldmatrix.sync.aligned.m8n8.x4.shared.b16 {%0,%1,%2,%3}, [%4];"
                 : "=r"(r0), "=r"(r1), "=r"(r2), "=r"(r3) : "r"(addr));
}
__device__ __forceinline__ void mma_fp16(float* c, const uint32_t* a, uint32_t b0, uint32_t b1) {
    asm volatile(
        "mma.sync.aligned.m16n8k16.row.col.f32.f16.f16.f32 "
        "{%0,%1,%2,%3}, {%4,%5,%6,%7}, {%8,%9}, {%0,%1,%2,%3};"
        : "+f"(c[0]), "+f"(c[1]), "+f"(c[2]), "+f"(c[3])
        : "r"(a[0]), "r"(a[1]), "r"(a[2]), "r"(a[3]), "r"(b0), "r"(b1));
}
__device__ __forceinline__ uint16_t h_bits(float f) {
    __half h = __float2half_rn(f);
    return *(uint16_t*)&h;
}
__device__ __forceinline__ uint32_t h2_bits(float x0, float x1) {
    return (uint32_t)h_bits(x0) | ((uint32_t)h_bits(x1) << 16);
}
__device__ __forceinline__ void sts16(uint32_t addr, uint16_t v) {
    asm volatile("st.shared.u16 [%0], %1;" :: "r"(addr), "h"(v));
}
__device__ __forceinline__ void sts128(uint32_t addr, uint4 v) {
    asm volatile("st.shared.v4.b32 [%0], {%1,%2,%3,%4};"
                 :: "r"(addr), "r"(v.x), "r"(v.y), "r"(v.z), "r"(v.w));
}
__device__ __forceinline__ void lds128(uint4& v, uint32_t addr) {
    asm volatile("ld.shared.v4.u32 {%0,%1,%2,%3}, [%4];"
                 : "=r"(v.x), "=r"(v.y), "=r"(v.z), "=r"(v.w) : "r"(addr));
}
__device__ __forceinline__ void lds32(uint32_t& v, uint32_t addr) {
    asm volatile("ld.shared.u32 %0, [%1];" : "=r"(v) : "r"(addr));
}
__device__ __forceinline__ uint32_t hmul2(uint32_t a, uint32_t b) {
    uint32_t d;
    asm("mul.rn.f16x2 %0, %1, %2;" : "=r"(d) : "r"(a), "r"(b));
    return d;
}

// ============================================================================
// Kernel 1 (merged pre-pass)
// ============================================================================
__global__ __launch_bounds__(256) void prepass(const float* __restrict__ x,
                                               const float* __restrict__ W,
                                               const int* __restrict__ adj,
                                               const float* __restrict__ mask) {
    __shared__ float tile[32][33];
    int blk = blockIdx.x, tid = threadIdx.x;
    if (blk < 2048) {
        size_t base = ((size_t)blk * 256 + tid) * 8;
        float4 v0 = *(const float4*)(x + base);
        float4 v1 = *(const float4*)(x + base + 4);
        *(uint4*)(g_xf + base) = make_uint4(h2_bits(v0.x, v0.y), h2_bits(v0.z, v0.w),
                                            h2_bits(v1.x, v1.y), h2_bits(v1.z, v1.w));
    } else if (blk < 3072) {
        int bb = blk - 2048;
        int n0 = (bb & 31) * 32, k0 = (bb >> 5) * 32;
        int tx = tid & 31, ty = tid >> 5;
#pragma unroll
        for (int i = 0; i < 4; i++)
            tile[ty + i * 8][tx] = W[(size_t)(k0 + ty + i * 8) * DOUT + n0 + tx];
        __syncthreads();
#pragma unroll
        for (int i = 0; i < 4; i++) {
            int n = n0 + ty + i * 8, k = k0 + tx;
            g_wt[(size_t)n * DIN + k] = h_bits(tile[tx][ty + i * 8]);
        }
    } else if (blk < 4096) {
        size_t base = ((size_t)(blk - 3072) * 256 + tid) * 8;
        int bi = (int)(base >> 9);
        uint32_t one = (mask[bi] > 0.f) ? 0x3C00u : 0u;   // fp16 1.0
        int4 a0 = *(const int4*)(adj + base);
        int4 a1 = *(const int4*)(adj + base + 4);
        uint32_t p0 = ((a0.x > 0) ? one : 0u) | (((a0.y > 0) ? one : 0u) << 16);
        uint32_t p1 = ((a0.z > 0) ? one : 0u) | (((a0.w > 0) ? one : 0u) << 16);
        uint32_t p2 = ((a1.x > 0) ? one : 0u) | (((a1.y > 0) ? one : 0u) << 16);
        uint32_t p3 = ((a1.z > 0) ? one : 0u) | (((a1.w > 0) ? one : 0u) << 16);
        *(uint4*)(g_adjf + base) = make_uint4(p0, p1, p2, p3);
    } else {
        g_colsum[(blk - 4096) * 256 + tid] = 0.f;
    }
}

// ============================================================================
// Kernel 2: projection GEMM, BM=128 BN=256 BK=128, 512 thr, 2-stage cp.async
//   Epilogue: smem transpose -> g_xst fp16, colsum atomics, AND s2 logits
//   (the 2 heads in this n-tile close their 128-channel dot inside the CTA)
// ============================================================================
#define PROJ_STAGE 98304          // A 2x16K + B 2x32K
#define PROJ_SMEM (2 * PROJ_STAGE + 2048)
__global__ __launch_bounds__(512) void proj_mma(const float* __restrict__ attw) {
    extern __shared__ char dsm[];
    uint32_t sb = (smem_u32(dsm) + 1023) & ~1023u;

    int tid = threadIdx.x, lane = tid & 31, wid = tid >> 5;
    int wm = wid & 3, wn = wid >> 2;  // 4 x 4 warps, each 32m x 64n
    int m_base = blockIdx.y * 128, n_base = blockIdx.x * 256;

    int srow = tid >> 3, skg = tid & 7;

    auto stage = [&](int ck, int s) {
        uint32_t base = sb + (uint32_t)s * PROJ_STAGE;
#pragma unroll
        for (int sub = 0; sub < 2; sub++) {
#pragma unroll
            for (int it = 0; it < 2; it++) {  // A: 128 rows
                int row = srow + it * 64;
                uint32_t so = swz((uint32_t)(row * 128 + skg * 16));
                size_t ga = (size_t)(m_base + row) * DIN + ck * 128 + sub * 64 + skg * 8;
                cpasync16(base + sub * 16384 + so, g_xf + ga);
            }
#pragma unroll
            for (int it = 0; it < 4; it++) {  // B: 256 rows
                int row = srow + it * 64;
                uint32_t so = swz((uint32_t)(row * 128 + skg * 16));
                size_t gb = (size_t)(n_base + row) * DIN + ck * 128 + sub * 64 + skg * 8;
                cpasync16(base + 32768 + sub * 32768 + so, g_wt + gb);
            }
        }
        cp_commit();
    };

    float acc[2][8][4] = {};

    stage(0, 0);
    for (int ck = 0; ck < 8; ck++) {
        if (ck + 1 < 8) {
            stage(ck + 1, (ck + 1) & 1);
            cp_wait<1>();
        } else {
            cp_wait<0>();
        }
        __syncthreads();
        uint32_t cbase = sb + (uint32_t)(ck & 1) * PROJ_STAGE;
#pragma unroll
        for (int sub = 0; sub < 2; sub++) {
            uint32_t AS = cbase + sub * 16384;
            uint32_t BS = cbase + 32768 + sub * 32768;
#pragma unroll
            for (int ks = 0; ks < 4; ks++) {
                uint32_t af[2][4];
#pragma unroll
                for (int mt = 0; mt < 2; mt++) {
                    int r = wm * 32 + mt * 16 + (lane & 15);
                    int kb = ks * 32 + (lane >> 4) * 16;
                    uint32_t off = swz((uint32_t)(r * 128 + kb));
                    ldsm4(af[mt][0], af[mt][1], af[mt][2], af[mt][3], AS + off);
                }
#pragma unroll
                for (int nq = 0; nq < 4; nq++) {
                    int r = wn * 64 + nq * 16 + (lane & 7) + ((lane >> 4) & 1) * 8;
                    int kb = ks * 32 + ((lane >> 3) & 1) * 16;
                    uint32_t off = swz((uint32_t)(r * 128 + kb));
                    uint32_t bs[4];
                    ldsm4(bs[0], bs[1], bs[2], bs[3], BS + off);
#pragma unroll
                    for (int mt = 0; mt < 2; mt++) {
                        mma_fp16(acc[mt][nq * 2],     af[mt], bs[0], bs[1]);
                        mma_fp16(acc[mt][nq * 2 + 1], af[mt], bs[2], bs[3]);
                    }
                }
            }
        }
        __syncthreads();
    }

    // ---- epilogue ----
    const int RS = 136;              // transpose row stride (halves): 128 + 8 pad
    uint32_t S2P = sb + 69632;       // 2 heads x 128 rows of float partials

    // s2 partials from fp32 accumulators (before any smem overwrite hazards)
    float p[2][2] = {};
#pragma unroll
    for (int mt = 0; mt < 2; mt++)
#pragma unroll
        for (int nt = 0; nt < 8; nt++) {
            int c = wn * 64 + nt * 8 + (lane & 3) * 2;
            float w0 = __ldg(attw + DATT + (c & 127));
            float w1 = __ldg(attw + DATT + ((c + 1) & 127));
            p[mt][0] += acc[mt][nt][0] * w0 + acc[mt][nt][1] * w1;
            p[mt][1] += acc[mt][nt][2] * w0 + acc[mt][nt][3] * w1;
        }
#pragma unroll
    for (int mt = 0; mt < 2; mt++) {
#pragma unroll
        for (int o = 1; o < 4; o <<= 1) {
            p[mt][0] += __shfl_xor_sync(0xFFFFFFFFu, p[mt][0], o);
            p[mt][1] += __shfl_xor_sync(0xFFFFFFFFu, p[mt][1], o);
        }
    }

    if (tid < 256) *(float*)(dsm + (S2P - smem_u32(dsm)) + tid * 4) = 0.f;

    // transpose stores (fp16) into smem
#pragma unroll
    for (int mt = 0; mt < 2; mt++)
#pragma unroll
        for (int nt = 0; nt < 8; nt++) {
            int r = wm * 32 + mt * 16 + (lane >> 2);
            int c = wn * 64 + nt * 8 + (lane & 3) * 2;
            float* a4 = acc[mt][nt];
            sts16(sb + (uint32_t)(c * RS + r) * 2,            h_bits(a4[0]));
            sts16(sb + (uint32_t)((c + 1) * RS + r) * 2,      h_bits(a4[1]));
            sts16(sb + (uint32_t)(c * RS + r + 8) * 2,        h_bits(a4[2]));
            sts16(sb + (uint32_t)((c + 1) * RS + r + 8) * 2,  h_bits(a4[3]));
        }
    __syncthreads();

    // s2 cross-warp accumulation (2 wn-warps per head)
    if ((lane & 3) == 0) {
        int head = wn >> 1;
        int r0 = wm * 32 + (lane >> 2);
        float* s2p = (float*)(dsm + (S2P - smem_u32(dsm)));
#pragma unroll
        for (int mt = 0; mt < 2; mt++) {
            atomicAdd(&s2p[head * 128 + r0 + mt * 16], p[mt][0]);
            atomicAdd(&s2p[head * 128 + r0 + mt * 16 + 8], p[mt][1]);
        }
    }

    // transpose read -> g_xst + colsum partials
    int b = m_base >> 9;
#pragma unroll
    for (int it = 0; it < 8; it++) {
        int task = it * 512 + tid;      // 4096 tasks: 256 c x 16 token-groups
        int c = task >> 4, g = task & 15;
        uint4 v;
        lds128(v, sb + (uint32_t)(c * RS + g * 8) * 2);
        *(uint4*)(g_xst + (size_t)(n_base + c) * NTOK + m_base + g * 8) = v;
        float2 f0 = __half22float2(*(__half2*)&v.x);
        float2 f1 = __half22float2(*(__half2*)&v.y);
        float2 f2 = __half22float2(*(__half2*)&v.z);
        float2 f3 = __half22float2(*(__half2*)&v.w);
        float s = f0.x + f0.y + f1.x + f1.y + f2.x + f2.y + f3.x + f3.y;
#pragma unroll
        for (int o = 8; o; o >>= 1) s += __shfl_xor_sync(0xFFFFFFFFu, s, o);
        if ((tid & 15) == 0) atomicAdd(&g_colsum[(b << 10) + n_base + c], s);
    }
    __syncthreads();

    // write s2 logits
    if (tid < 256) {
        int head = tid >> 7, row = tid & 127;
        int h = (n_base >> 7) + head;
        float v = *(float*)(dsm + (S2P - smem_u32(dsm)) + tid * 4);
        g_s2[(size_t)(b * H_ + h) * S_ + (m_base & 511) + row] = v;
    }
}

// ============================================================================
// Kernel 3: tiny max + exp + mask  (block per (b,h), 512 threads)
// ============================================================================
__global__ __launch_bounds__(512) void expk(const float* __restrict__ mask) {
    __shared__ float red[16];
    int bh = blockIdx.x;
    int b = bh >> 3;
    int tid = threadIdx.x, wid = tid >> 5, lane = tid & 31;
    float v = g_s2[(size_t)bh * S_ + tid];
    float m = v;
#pragma unroll
    for (int o = 16; o; o >>= 1) m = fmaxf(m, __shfl_xor_sync(0xFFFFFFFFu, m, o));
    if (lane == 0) red[wid] = m;
    __syncthreads();
    if (wid == 0) {
        float t = (lane < 16) ? red[lane] : -INFINITY;
#pragma unroll
        for (int o = 8; o; o >>= 1) t = fmaxf(t, __shfl_xor_sync(0xFFFFFFFFu, t, o));
        if (lane == 0) red[0] = t;
    }
    __syncthreads();
    m = red[0];
    float mj = mask[b * S_ + tid] > 0.f ? 1.f : 0.f;
    g_e2h[(size_t)bh * S_ + tid] = h_bits(mj * expf(v - m));
}

// ============================================================================
// Kernel 4: attention GEMM, 512 thr, BM=256(i) BN=128(c) BK=128, grid=128
//   e2 folded into A fragments; ones-column denominator; fused normalize
// ============================================================================
#define ATT_STAGE 98304           // adj 2x32K + xst 2x16K
#define ATT_SMEM (1024 + 2 * ATT_STAGE + 1024)
__global__ __launch_bounds__(512) void att_mma(float* __restrict__ out) {
    extern __shared__ char dsm[];
    uint32_t sb = (smem_u32(dsm) + 1023) & ~1023u;
    uint32_t E2 = sb;
    uint32_t stage0 = sb + 1024;

    int tid = threadIdx.x, lane = tid & 31, wid = tid >> 5;
    int wm = wid & 7, wn = wid >> 3;   // 8 x 2 warps: 32 i x 64 c each
    int h = blockIdx.x, i0 = blockIdx.y * 256, b = blockIdx.z;
    int c0 = h * DATT;

    // stage e2 fp16 (512 values = 1 KB)
    if (tid < 64) {
        uint4 v = ((const uint4*)(g_e2h + (size_t)(b * H_ + h) * S_))[tid];
        sts128(E2 + tid * 16, v);
    }

    int srow = tid >> 3, skg = tid & 7;

    auto stage = [&](int ck, int s) {
        uint32_t base = stage0 + (uint32_t)s * ATT_STAGE;
#pragma unroll
        for (int sub = 0; sub < 2; sub++) {
#pragma unroll
            for (int it = 0; it < 4; it++) {   // adjacency: 256 rows
                int row = srow + it * 64;
                uint32_t so = swz((uint32_t)(row * 128 + skg * 16));
                size_t ga = (size_t)(b * S_ + i0 + row) * S_ + ck * 128 + sub * 64 + skg * 8;
                cpasync16(base + sub * 32768 + so, g_adjf + ga);
            }
#pragma unroll
            for (int it = 0; it < 2; it++) {   // xst: 128 rows
                int row = srow + it * 64;
                uint32_t so = swz((uint32_t)(row * 128 + skg * 16));
                size_t gb = (size_t)(c0 + row) * NTOK + b * S_ + ck * 128 + sub * 64 + skg * 8;
                cpasync16(base + 65536 + sub * 16384 + so, g_xst + gb);
            }
        }
        cp_commit();
    };

    float acc[2][8][4] = {};
    float acc_d[2][4] = {};
    int nn = lane >> 2;

    stage(0, 0);
    for (int kc = 0; kc < 4; kc++) {
        if (kc + 1 < 4) {
            stage(kc + 1, (kc + 1) & 1);
            cp_wait<1>();
        } else {
            cp_wait<0>();
        }
        __syncthreads();
        uint32_t cbase = stage0 + (uint32_t)(kc & 1) * ATT_STAGE;
#pragma unroll
        for (int sub = 0; sub < 2; sub++) {
            uint32_t AD = cbase + sub * 32768;
            uint32_t BS = cbase + 65536 + sub * 16384;
#pragma unroll
            for (int ks = 0; ks < 4; ks++) {
                uint32_t ad[2][4];
#pragma unroll
                for (int mt = 0; mt < 2; mt++) {
                    int r = wm * 32 + mt * 16 + (lane & 15);
                    int kb = ks * 32 + (lane >> 4) * 16;
                    ldsm4(ad[mt][0], ad[mt][1], ad[mt][2], ad[mt][3],
                          AD + swz((uint32_t)(r * 128 + kb)));
                }
                // fold e2[j] into A fragments (adj in {0,1} -> exact fp16)
                {
                    int kj = kc * 128 + sub * 64 + ks * 16 + (lane & 3) * 2;
                    uint32_t ea, eb;
                    lds32(ea, E2 + kj * 2);
                    lds32(eb, E2 + kj * 2 + 16);
#pragma unroll
                    for (int mt = 0; mt < 2; mt++) {
                        ad[mt][0] = hmul2(ad[mt][0], ea);
                        ad[mt][1] = hmul2(ad[mt][1], ea);
                        ad[mt][2] = hmul2(ad[mt][2], eb);
                        ad[mt][3] = hmul2(ad[mt][3], eb);
                    }
                }
                // denominator: B = ones column at n=0
                {
                    uint32_t v = (nn == 0) ? 0x3C003C00u : 0u;
#pragma unroll
                    for (int mt = 0; mt < 2; mt++)
                        mma_fp16(acc_d[mt], ad[mt], v, v);
                }
#pragma unroll
                for (int nq = 0; nq < 4; nq++) {
                    int r = wn * 64 + nq * 16 + (lane & 7) + ((lane >> 4) & 1) * 8;
                    int kb = ks * 32 + ((lane >> 3) & 1) * 16;
                    uint32_t off = swz((uint32_t)(r * 128 + kb));
                    uint32_t bs[4];
                    ldsm4(bs[0], bs[1], bs[2], bs[3], BS + off);
#pragma unroll
                    for (int mt = 0; mt < 2; mt++) {
                        mma_fp16(acc[mt][nq * 2],     ad[mt], bs[0], bs[1]);
                        mma_fp16(acc[mt][nq * 2 + 1], ad[mt], bs[2], bs[3]);
                    }
                }
            }
        }
        __syncthreads();
    }

    // epilogue: denom = col0 of acc_d (held by lane%4==0), normalize + fallback
    const float* cs = g_colsum + (b << 10);
#pragma unroll
    for (int mt = 0; mt < 2; mt++) {
        int r0 = i0 + wm * 32 + mt * 16 + (lane >> 2);
        float d0 = __shfl_sync(0xFFFFFFFFu, acc_d[mt][0], lane & 28);
        float d1 = __shfl_sync(0xFFFFFFFFu, acc_d[mt][2], lane & 28);
        float q0 = (d0 > 0.f) ? (1.0f / d0) : 0.f;
        float q1 = (d1 > 0.f) ? (1.0f / d1) : 0.f;
#pragma unroll
        for (int nt = 0; nt < 8; nt++) {
            int c = c0 + wn * 64 + nt * 8 + (lane & 3) * 2;
            float* a4 = acc[mt][nt];
            float2 o0, o1;
            if (d0 > 0.f) { o0 = make_float2(a4[0] * q0, a4[1] * q0); }
            else {
                float2 f = *(const float2*)(cs + c);
                o0 = make_float2(f.x * (1.0f / S_), f.y * (1.0f / S_));
            }
            if (d1 > 0.f) { o1 = make_float2(a4[2] * q1, a4[3] * q1); }
            else {
                float2 f = *(const float2*)(cs + c);
                o1 = make_float2(f.x * (1.0f / S_), f.y * (1.0f / S_));
            }
            *(float2*)(out + (size_t)(b * S_ + r0) * DOUT + c) = o0;
            *(float2*)(out + (size_t)(b * S_ + r0 + 8) * DOUT + c) = o1;
        }
    }
}

// ============================================================================
extern "C" void kernel_launch(void* const* d_in, const int* in_sizes, int n_in,
                              void* d_out, int out_size) {
    const float* x    = (const float*)d_in[0];
    const float* mask = (const float*)d_in[1];
    const int*   adj  = (const int*)d_in[2];
    const float* W    = (const float*)d_in[3];
    const float* attw = (const float*)d_in[4];
    float* out = (float*)d_out;

    cudaFuncSetAttribute(proj_mma, cudaFuncAttributeMaxDynamicSharedMemorySize, PROJ_SMEM);
    cudaFuncSetAttribute(att_mma, cudaFuncAttributeMaxDynamicSharedMemorySize, ATT_SMEM);

    prepass<<<4128, 256>>>(x, W, adj, mask);
    proj_mma<<<dim3(DOUT / 256, NTOK / 128), 512, PROJ_SMEM>>>(attw);
    expk<<<B_ * H_, 512>>>(mask);
    att_mma<<<dim3(H_, S_ / 256, B_), 512, ATT_SMEM>>>(out);
}